// round 1
// baseline (speedup 1.0000x reference)
#include <cuda_runtime.h>
#include <math.h>
#include <float.h>

#define Dm 1024
#define Sm 2048
#define Bm 2
#define Hm 16
#define DHm 64
#define BHm (Bm * Hm)

// Scratch (static device arrays; no allocations in kernel_launch)
__device__ float g_q[BHm * DHm * Sm];    // [b*H+h][d][s]  (transposed for attention)
__device__ float g_k[BHm * DHm * Sm];    // [b*H+h][d][s]
__device__ float g_v[BHm * Sm * DHm];    // [b*H+h][s][d]
__device__ float g_ctx[Bm * Sm * Dm];    // [b][s][h*64+d]
__device__ float g_y[Bm * Sm * Dm];      // pre-LN residual sum

// ---------------------------------------------------------------------------
// Shared GEMM mainloop: C[128x128] tile of A[M,K] @ W[N,K]^T, K=1024
// 256 threads, 8x8 fragment per thread, BK=16, register prefetch.
// ---------------------------------------------------------------------------
__device__ __forceinline__ void gemm_main(const float* __restrict__ A,
                                          const float* __restrict__ Wt,
                                          float acc[8][8])
{
    __shared__ float As[16 * 128];
    __shared__ float Bs[16 * 128];

    const int tid = threadIdx.x;
    const int tr  = tid >> 4;        // 0..15
    const int tc  = tid & 15;        // 0..15
    const int m0  = blockIdx.y * 128;
    const int n0  = blockIdx.x * 128;
    const int r0  = tid >> 2;        // 0..63
    const int k4  = (tid & 3) * 4;   // 0,4,8,12

    const float* Ap = A  + (size_t)(m0 + r0) * Dm + k4;
    const float* Bp = Wt + (size_t)(n0 + r0) * Dm + k4;

    float4 fa0 = *(const float4*)(Ap);
    float4 fa1 = *(const float4*)(Ap + 64 * Dm);
    float4 fb0 = *(const float4*)(Bp);
    float4 fb1 = *(const float4*)(Bp + 64 * Dm);

    for (int kt = 0; kt < 64; ++kt) {
        // store current K-slab to smem (transposed: [k][m] / [k][n])
        As[(k4 + 0) * 128 + r0]      = fa0.x;
        As[(k4 + 1) * 128 + r0]      = fa0.y;
        As[(k4 + 2) * 128 + r0]      = fa0.z;
        As[(k4 + 3) * 128 + r0]      = fa0.w;
        As[(k4 + 0) * 128 + r0 + 64] = fa1.x;
        As[(k4 + 1) * 128 + r0 + 64] = fa1.y;
        As[(k4 + 2) * 128 + r0 + 64] = fa1.z;
        As[(k4 + 3) * 128 + r0 + 64] = fa1.w;
        Bs[(k4 + 0) * 128 + r0]      = fb0.x;
        Bs[(k4 + 1) * 128 + r0]      = fb0.y;
        Bs[(k4 + 2) * 128 + r0]      = fb0.z;
        Bs[(k4 + 3) * 128 + r0]      = fb0.w;
        Bs[(k4 + 0) * 128 + r0 + 64] = fb1.x;
        Bs[(k4 + 1) * 128 + r0 + 64] = fb1.y;
        Bs[(k4 + 2) * 128 + r0 + 64] = fb1.z;
        Bs[(k4 + 3) * 128 + r0 + 64] = fb1.w;
        __syncthreads();

        if (kt < 63) {
            const float* Ap2 = Ap + (kt + 1) * 16;
            const float* Bp2 = Bp + (kt + 1) * 16;
            fa0 = *(const float4*)(Ap2);
            fa1 = *(const float4*)(Ap2 + 64 * Dm);
            fb0 = *(const float4*)(Bp2);
            fb1 = *(const float4*)(Bp2 + 64 * Dm);
        }

        #pragma unroll
        for (int k = 0; k < 16; ++k) {
            float4 a0 = *(const float4*)&As[k * 128 + tr * 4];
            float4 a1 = *(const float4*)&As[k * 128 + tr * 4 + 64];
            float4 b0 = *(const float4*)&Bs[k * 128 + tc * 4];
            float4 b1 = *(const float4*)&Bs[k * 128 + tc * 4 + 64];
            float av[8] = {a0.x, a0.y, a0.z, a0.w, a1.x, a1.y, a1.z, a1.w};
            float bv[8] = {b0.x, b0.y, b0.z, b0.w, b1.x, b1.y, b1.z, b1.w};
            #pragma unroll
            for (int i = 0; i < 8; ++i)
                #pragma unroll
                for (int j = 0; j < 8; ++j)
                    acc[i][j] += av[i] * bv[j];
        }
        __syncthreads();
    }
}

// ---------------------------------------------------------------------------
// QKV projection. grid = (8, 32, 3): z selects Q/K/V.
// Q,K stored transposed [bh][d][s]; V stored [bh][s][d].
// ---------------------------------------------------------------------------
__global__ void __launch_bounds__(256)
gemm_qkv_kernel(const float* __restrict__ x,
                const float* __restrict__ Wq, const float* __restrict__ bq,
                const float* __restrict__ Wk, const float* __restrict__ bk,
                const float* __restrict__ Wv, const float* __restrict__ bv)
{
    const int z = blockIdx.z;
    const float* W    = (z == 0) ? Wq : (z == 1) ? Wk : Wv;
    const float* bias = (z == 0) ? bq : (z == 1) ? bk : bv;

    float acc[8][8];
    #pragma unroll
    for (int i = 0; i < 8; ++i)
        #pragma unroll
        for (int j = 0; j < 8; ++j) acc[i][j] = 0.f;

    gemm_main(x, W, acc);

    const int tid = threadIdx.x;
    const int tr  = tid >> 4;
    const int tc  = tid & 15;
    const int m0  = blockIdx.y * 128;
    const int n0  = blockIdx.x * 128;
    const int b   = m0 >> 11;                 // constant across the block

    if (z < 2) {
        float* dst = (z == 0) ? g_q : g_k;
        // layout [bh][d][s]: vectorize along s (rows i)
        #pragma unroll
        for (int j = 0; j < 8; ++j) {
            const int nj = n0 + tc * 4 + (j & 3) + ((j >> 2) * 64);
            const int h  = nj >> 6, dd = nj & 63;
            const float bb = bias[nj];
            #pragma unroll
            for (int half = 0; half < 2; ++half) {
                const int mi0 = m0 + half * 64 + tr * 4;
                const int s0  = mi0 & 2047;
                float4 v;
                v.x = acc[half * 4 + 0][j] + bb;
                v.y = acc[half * 4 + 1][j] + bb;
                v.z = acc[half * 4 + 2][j] + bb;
                v.w = acc[half * 4 + 3][j] + bb;
                *(float4*)&dst[(((size_t)(b * Hm + h) * DHm + dd) * Sm) + s0] = v;
            }
        }
    } else {
        // V layout [bh][s][d]: vectorize along d (cols j)
        #pragma unroll
        for (int i = 0; i < 8; ++i) {
            const int mi = m0 + tr * 4 + (i & 3) + ((i >> 2) * 64);
            const int s  = mi & 2047;
            #pragma unroll
            for (int jq = 0; jq < 2; ++jq) {
                const int nj0 = n0 + tc * 4 + jq * 64;
                const int h = nj0 >> 6, dd0 = nj0 & 63;
                float4 v;
                v.x = acc[i][jq * 4 + 0] + bias[nj0 + 0];
                v.y = acc[i][jq * 4 + 1] + bias[nj0 + 1];
                v.z = acc[i][jq * 4 + 2] + bias[nj0 + 2];
                v.w = acc[i][jq * 4 + 3] + bias[nj0 + 3];
                *(float4*)&g_v[(((size_t)(b * Hm + h) * Sm + s) * DHm) + dd0] = v;
            }
        }
    }
}

// ---------------------------------------------------------------------------
// Output projection + residual: y = ctx @ Wo^T + bo + x
// ---------------------------------------------------------------------------
__global__ void __launch_bounds__(256)
gemm_oproj_kernel(const float* __restrict__ ctx,
                  const float* __restrict__ Wo, const float* __restrict__ bo,
                  const float* __restrict__ x)
{
    float acc[8][8];
    #pragma unroll
    for (int i = 0; i < 8; ++i)
        #pragma unroll
        for (int j = 0; j < 8; ++j) acc[i][j] = 0.f;

    gemm_main(ctx, Wo, acc);

    const int tid = threadIdx.x;
    const int tr  = tid >> 4;
    const int tc  = tid & 15;
    const int m0  = blockIdx.y * 128;
    const int n0  = blockIdx.x * 128;

    #pragma unroll
    for (int i = 0; i < 8; ++i) {
        const int mi = m0 + tr * 4 + (i & 3) + ((i >> 2) * 64);
        #pragma unroll
        for (int jq = 0; jq < 2; ++jq) {
            const int nj0 = n0 + tc * 4 + jq * 64;
            const size_t off = (size_t)mi * Dm + nj0;
            float4 r = *(const float4*)&x[off];
            float4 v;
            v.x = acc[i][jq * 4 + 0] + bo[nj0 + 0] + r.x;
            v.y = acc[i][jq * 4 + 1] + bo[nj0 + 1] + r.y;
            v.z = acc[i][jq * 4 + 2] + bo[nj0 + 2] + r.z;
            v.w = acc[i][jq * 4 + 3] + bo[nj0 + 3] + r.w;
            *(float4*)&g_y[off] = v;
        }
    }
}

// ---------------------------------------------------------------------------
// Causal flash attention, fp32. grid = (S/64 q-tiles, B*H). 256 threads.
// Q,K come pre-transposed [bh][d][s]; V natural [bh][s][d].
// smem: Qt[64][64], KP[64][64] (K^T then reused for P), Vs[64][64] = 48KB.
// Thread (ty,tx) owns score rows ty*4..+3, score cols tx*4..+3, out dims tx*4..+3.
// ---------------------------------------------------------------------------
__global__ void __launch_bounds__(256)
attn_kernel(const float* __restrict__ Qg, const float* __restrict__ Kg,
            const float* __restrict__ Vg, float* __restrict__ ctx)
{
    __shared__ float Qt[64 * 64];
    __shared__ float KP[64 * 64];
    __shared__ float Vs[64 * 64];

    const int tid = threadIdx.x;
    const int ty  = tid >> 4;
    const int tx  = tid & 15;
    const int bh  = blockIdx.y;
    const int qb  = blockIdx.x;
    const int qi0 = qb * 64;

    const float* Qbh = Qg + (size_t)bh * DHm * Sm;
    const float* Kbh = Kg + (size_t)bh * DHm * Sm;
    const float* Vbh = Vg + (size_t)bh * Sm * DHm;

    // load Q tile transposed layout [d][i]
    #pragma unroll
    for (int idx = tid; idx < 1024; idx += 256) {
        const int d = idx >> 4, i4 = (idx & 15) * 4;
        *(float4*)&Qt[d * 64 + i4] = *(const float4*)&Qbh[(size_t)d * Sm + qi0 + i4];
    }

    float m_i[4], l_i[4], o[4][4];
    #pragma unroll
    for (int ii = 0; ii < 4; ++ii) {
        m_i[ii] = -1e30f;
        l_i[ii] = 0.f;
        o[ii][0] = o[ii][1] = o[ii][2] = o[ii][3] = 0.f;
    }
    __syncthreads();

    for (int kt = 0; kt <= qb; ++kt) {
        const int kj0 = kt * 64;
        // load K^T tile [d][j] and V tile [j][d]
        #pragma unroll
        for (int idx = tid; idx < 1024; idx += 256) {
            const int d = idx >> 4, j4 = (idx & 15) * 4;
            *(float4*)&KP[d * 64 + j4] = *(const float4*)&Kbh[(size_t)d * Sm + kj0 + j4];
        }
        #pragma unroll
        for (int idx = tid; idx < 1024; idx += 256) {
            const int j = idx >> 4, d4 = (idx & 15) * 4;
            *(float4*)&Vs[j * 64 + d4] = *(const float4*)&Vbh[(size_t)(kj0 + j) * DHm + d4];
        }
        __syncthreads();

        // scores: s[i][j] = sum_d Qt[d][i] * Kt[d][j]
        float s[4][4];
        #pragma unroll
        for (int ii = 0; ii < 4; ++ii)
            s[ii][0] = s[ii][1] = s[ii][2] = s[ii][3] = 0.f;

        #pragma unroll 16
        for (int d = 0; d < 64; ++d) {
            float4 q4 = *(const float4*)&Qt[d * 64 + ty * 4];
            float4 k4 = *(const float4*)&KP[d * 64 + tx * 4];
            float qa[4] = {q4.x, q4.y, q4.z, q4.w};
            float ka[4] = {k4.x, k4.y, k4.z, k4.w};
            #pragma unroll
            for (int ii = 0; ii < 4; ++ii)
                #pragma unroll
                for (int jj = 0; jj < 4; ++jj)
                    s[ii][jj] += qa[ii] * ka[jj];
        }

        const bool diag = (kt == qb);
        #pragma unroll
        for (int ii = 0; ii < 4; ++ii)
            #pragma unroll
            for (int jj = 0; jj < 4; ++jj) {
                float v = s[ii][jj] * 0.125f;  // 1/sqrt(64)
                if (diag && (tx * 4 + jj > ty * 4 + ii)) v = -1e30f;
                s[ii][jj] = v;
            }

        // online softmax update
        float pr[4][4];
        #pragma unroll
        for (int ii = 0; ii < 4; ++ii) {
            float mx = fmaxf(fmaxf(s[ii][0], s[ii][1]), fmaxf(s[ii][2], s[ii][3]));
            #pragma unroll
            for (int off = 8; off > 0; off >>= 1)
                mx = fmaxf(mx, __shfl_xor_sync(0xffffffffu, mx, off));
            const float mn    = fmaxf(m_i[ii], mx);
            const float alpha = __expf(m_i[ii] - mn);
            m_i[ii] = mn;
            float ls = 0.f;
            #pragma unroll
            for (int jj = 0; jj < 4; ++jj) {
                const float p = __expf(s[ii][jj] - mn);
                pr[ii][jj] = p;
                ls += p;
            }
            #pragma unroll
            for (int off = 8; off > 0; off >>= 1)
                ls += __shfl_xor_sync(0xffffffffu, ls, off);
            l_i[ii] = l_i[ii] * alpha + ls;
            o[ii][0] *= alpha; o[ii][1] *= alpha; o[ii][2] *= alpha; o[ii][3] *= alpha;
        }

        __syncthreads();   // all reads of K^T done; reuse buffer for P
        #pragma unroll
        for (int ii = 0; ii < 4; ++ii)
            *(float4*)&KP[(ty * 4 + ii) * 64 + tx * 4] =
                make_float4(pr[ii][0], pr[ii][1], pr[ii][2], pr[ii][3]);
        __syncthreads();

        // o[i][dc] += sum_j P[i][j] * V[j][dc]
        #pragma unroll 16
        for (int j = 0; j < 64; ++j) {
            float4 v4 = *(const float4*)&Vs[j * 64 + tx * 4];
            #pragma unroll
            for (int ii = 0; ii < 4; ++ii) {
                const float p = KP[(ty * 4 + ii) * 64 + j];
                o[ii][0] += p * v4.x;
                o[ii][1] += p * v4.y;
                o[ii][2] += p * v4.z;
                o[ii][3] += p * v4.w;
            }
        }
        __syncthreads();   // protect KP/Vs before next tile load
    }

    const int b = bh >> 4, h = bh & 15;
    #pragma unroll
    for (int ii = 0; ii < 4; ++ii) {
        const float inv  = 1.0f / l_i[ii];
        const int   srow = qi0 + ty * 4 + ii;
        float4 r = make_float4(o[ii][0] * inv, o[ii][1] * inv,
                               o[ii][2] * inv, o[ii][3] * inv);
        *(float4*)&ctx[((size_t)(b * Sm + srow)) * Dm + h * DHm + tx * 4] = r;
    }
}

// ---------------------------------------------------------------------------
// LayerNorm over last dim (1024). One block per row, 256 threads x 4 floats.
// ---------------------------------------------------------------------------
__global__ void __launch_bounds__(256)
ln_kernel(const float* __restrict__ y, const float* __restrict__ gam,
          const float* __restrict__ bet, float* __restrict__ out)
{
    __shared__ float red[2][8];
    const int row = blockIdx.x;
    const int tid = threadIdx.x;

    const float4 v = *(const float4*)&y[(size_t)row * Dm + tid * 4];
    float s  = v.x + v.y + v.z + v.w;
    float ss = v.x * v.x + v.y * v.y + v.z * v.z + v.w * v.w;

    #pragma unroll
    for (int off = 16; off > 0; off >>= 1) {
        s  += __shfl_xor_sync(0xffffffffu, s, off);
        ss += __shfl_xor_sync(0xffffffffu, ss, off);
    }
    const int wid = tid >> 5, lane = tid & 31;
    if (lane == 0) { red[0][wid] = s; red[1][wid] = ss; }
    __syncthreads();
    if (tid == 0) {
        float S = 0.f, SS = 0.f;
        #pragma unroll
        for (int w = 0; w < 8; ++w) { S += red[0][w]; SS += red[1][w]; }
        red[0][0] = S; red[1][0] = SS;
    }
    __syncthreads();

    const float mu   = red[0][0] * (1.0f / Dm);
    const float var  = red[1][0] * (1.0f / Dm) - mu * mu;
    const float rstd = rsqrtf(var + 1e-5f);

    const float4 g4 = *(const float4*)&gam[tid * 4];
    const float4 b4 = *(const float4*)&bet[tid * 4];
    float4 r;
    r.x = (v.x - mu) * rstd * g4.x + b4.x;
    r.y = (v.y - mu) * rstd * g4.y + b4.y;
    r.z = (v.z - mu) * rstd * g4.z + b4.z;
    r.w = (v.w - mu) * rstd * g4.w + b4.w;
    *(float4*)&out[(size_t)row * Dm + tid * 4] = r;
}

// ---------------------------------------------------------------------------
extern "C" void kernel_launch(void* const* d_in, const int* in_sizes, int n_in,
                              void* d_out, int out_size)
{
    const float* x    = (const float*)d_in[0];
    const float* Wq   = (const float*)d_in[1];
    const float* bq   = (const float*)d_in[2];
    const float* Wk   = (const float*)d_in[3];
    const float* bk   = (const float*)d_in[4];
    const float* Wv   = (const float*)d_in[5];
    const float* bv   = (const float*)d_in[6];
    const float* Wo   = (const float*)d_in[7];
    const float* bo   = (const float*)d_in[8];
    const float* ln_g = (const float*)d_in[9];
    const float* ln_b = (const float*)d_in[10];
    float* out = (float*)d_out;

    float *q_p, *k_p, *v_p, *ctx_p, *y_p;
    cudaGetSymbolAddress((void**)&q_p,   g_q);
    cudaGetSymbolAddress((void**)&k_p,   g_k);
    cudaGetSymbolAddress((void**)&v_p,   g_v);
    cudaGetSymbolAddress((void**)&ctx_p, g_ctx);
    cudaGetSymbolAddress((void**)&y_p,   g_y);

    gemm_qkv_kernel<<<dim3(8, 32, 3), 256>>>(x, Wq, bq, Wk, bk, Wv, bv);
    attn_kernel<<<dim3(32, 32), 256>>>(q_p, k_p, v_p, ctx_p);
    gemm_oproj_kernel<<<dim3(8, 32), 256>>>(ctx_p, Wo, bo, x);
    ln_kernel<<<4096, 256>>>(y_p, ln_g, ln_b, out);
}

// round 2
// speedup vs baseline: 1.4796x; 1.4796x over previous
#include <cuda_runtime.h>
#include <math.h>
#include <float.h>
#include <stdint.h>

#define Dm 1024
#define Sm 2048
#define Bm 2
#define Hm 16
#define DHm 64
#define BHm (Bm * Hm)

// Scratch (static device arrays; no allocations in kernel_launch)
__device__ float g_q[BHm * DHm * Sm];    // [b*H+h][d][s]  (transposed for attention)
__device__ float g_k[BHm * DHm * Sm];    // [b*H+h][d][s]
__device__ float g_v[BHm * Sm * DHm];    // [b*H+h][s][d]
__device__ float g_ctx[Bm * Sm * Dm];    // [b][s][h*64+d]
__device__ float g_y[Bm * Sm * Dm];      // pre-LN residual sum

// ---------------------------------------------------------------------------
// tf32 helpers
// ---------------------------------------------------------------------------
__device__ __forceinline__ uint32_t f2tf(float x) {
    uint32_t r;
    asm("cvt.rna.tf32.f32 %0, %1;" : "=r"(r) : "f"(x));
    return r;
}

__device__ __forceinline__ void mma_tf32(float c[4], const uint32_t a[4], const uint32_t b[2]) {
    asm volatile(
        "mma.sync.aligned.m16n8k8.row.col.f32.tf32.tf32.f32 "
        "{%0,%1,%2,%3}, {%4,%5,%6,%7}, {%8,%9}, {%0,%1,%2,%3};"
        : "+f"(c[0]), "+f"(c[1]), "+f"(c[2]), "+f"(c[3])
        : "r"(a[0]), "r"(a[1]), "r"(a[2]), "r"(a[3]), "r"(b[0]), "r"(b[1]));
}

#define SSTR 20   // smem row stride in words (conflict-free for fragment loads)

// ---------------------------------------------------------------------------
// tf32 GEMM mainloop: C[128x128] tile of A[M,K] @ W[N,K]^T, K=1024.
// 256 threads = 8 warps, each warp 64x32 (4 m-frags x 4 n-frags of m16n8k8).
// acc[mi][ni][4]: c0=(r,c2) c1=(r,c2+1) c2=(r+8,c2) c3=(r+8,c2+1),
//   r = lane>>2, c2 = (lane&3)*2.
// ---------------------------------------------------------------------------
__device__ __forceinline__ void gemm_main_tf32(const float* __restrict__ A,
                                               const float* __restrict__ Wt,
                                               float acc[4][4][4])
{
    __shared__ __align__(16) uint32_t As[128 * SSTR];
    __shared__ __align__(16) uint32_t Bs[128 * SSTR];

    const int tid  = threadIdx.x;
    const int lane = tid & 31;
    const int warp = tid >> 5;
    const int wm   = (warp >> 2) * 64;   // 0 or 64
    const int wn   = (warp & 3) * 32;    // 0,32,64,96
    const int gid  = lane >> 2;          // 0..7
    const int qid  = lane & 3;           // 0..3
    const int m0   = blockIdx.y * 128;
    const int n0   = blockIdx.x * 128;
    const int r0   = tid >> 2;           // 0..63
    const int k4   = (tid & 3) * 4;      // 0,4,8,12

    const float* Ap = A  + (size_t)(m0 + r0) * Dm + k4;
    const float* Bp = Wt + (size_t)(n0 + r0) * Dm + k4;

    float4 fa0 = *(const float4*)(Ap);
    float4 fa1 = *(const float4*)(Ap + 64 * Dm);
    float4 fb0 = *(const float4*)(Bp);
    float4 fb1 = *(const float4*)(Bp + 64 * Dm);

    for (int kt = 0; kt < 64; ++kt) {
        // convert to tf32 and store current K-slab (layout [row][k], stride 20)
        uint4 u;
        u.x = f2tf(fa0.x); u.y = f2tf(fa0.y); u.z = f2tf(fa0.z); u.w = f2tf(fa0.w);
        *(uint4*)&As[r0 * SSTR + k4] = u;
        u.x = f2tf(fa1.x); u.y = f2tf(fa1.y); u.z = f2tf(fa1.z); u.w = f2tf(fa1.w);
        *(uint4*)&As[(r0 + 64) * SSTR + k4] = u;
        u.x = f2tf(fb0.x); u.y = f2tf(fb0.y); u.z = f2tf(fb0.z); u.w = f2tf(fb0.w);
        *(uint4*)&Bs[r0 * SSTR + k4] = u;
        u.x = f2tf(fb1.x); u.y = f2tf(fb1.y); u.z = f2tf(fb1.z); u.w = f2tf(fb1.w);
        *(uint4*)&Bs[(r0 + 64) * SSTR + k4] = u;
        __syncthreads();

        if (kt < 63) {
            const float* Ap2 = Ap + (kt + 1) * 16;
            const float* Bp2 = Bp + (kt + 1) * 16;
            fa0 = *(const float4*)(Ap2);
            fa1 = *(const float4*)(Ap2 + 64 * Dm);
            fb0 = *(const float4*)(Bp2);
            fb1 = *(const float4*)(Bp2 + 64 * Dm);
        }

        #pragma unroll
        for (int ks = 0; ks < 2; ++ks) {
            const int kb = ks * 8 + qid;
            uint32_t a[4][4];
            uint32_t b[4][2];
            #pragma unroll
            for (int mi = 0; mi < 4; ++mi) {
                const uint32_t* p = &As[(wm + mi * 16 + gid) * SSTR + kb];
                a[mi][0] = p[0];
                a[mi][1] = p[8 * SSTR];
                a[mi][2] = p[4];
                a[mi][3] = p[8 * SSTR + 4];
            }
            #pragma unroll
            for (int ni = 0; ni < 4; ++ni) {
                const uint32_t* p = &Bs[(wn + ni * 8 + gid) * SSTR + kb];
                b[ni][0] = p[0];
                b[ni][1] = p[4];
            }
            #pragma unroll
            for (int mi = 0; mi < 4; ++mi)
                #pragma unroll
                for (int ni = 0; ni < 4; ++ni)
                    mma_tf32(acc[mi][ni], a[mi], b[ni]);
        }
        __syncthreads();
    }
}

// ---------------------------------------------------------------------------
// QKV projection. grid = (8, 32, 3): z selects Q/K/V.
// Q,K stored transposed [bh][d][s]; V stored [bh][s][d].
// ---------------------------------------------------------------------------
__global__ void __launch_bounds__(256)
gemm_qkv_kernel(const float* __restrict__ x,
                const float* __restrict__ Wq, const float* __restrict__ bq,
                const float* __restrict__ Wk, const float* __restrict__ bk,
                const float* __restrict__ Wv, const float* __restrict__ bv)
{
    const int z = blockIdx.z;
    const float* W    = (z == 0) ? Wq : (z == 1) ? Wk : Wv;
    const float* bias = (z == 0) ? bq : (z == 1) ? bk : bv;

    float acc[4][4][4];
    #pragma unroll
    for (int mi = 0; mi < 4; ++mi)
        #pragma unroll
        for (int ni = 0; ni < 4; ++ni) {
            acc[mi][ni][0] = 0.f; acc[mi][ni][1] = 0.f;
            acc[mi][ni][2] = 0.f; acc[mi][ni][3] = 0.f;
        }

    gemm_main_tf32(x, W, acc);

    const int tid  = threadIdx.x;
    const int lane = tid & 31;
    const int warp = tid >> 5;
    const int wm   = (warp >> 2) * 64;
    const int wn   = (warp & 3) * 32;
    const int gid  = lane >> 2;
    const int qid  = lane & 3;
    const int m0   = blockIdx.y * 128;
    const int n0   = blockIdx.x * 128;

    if (z < 2) {
        float* dst = (z == 0) ? g_q : g_k;
        // layout [bh][d][s]
        #pragma unroll
        for (int mi = 0; mi < 4; ++mi) {
            #pragma unroll
            for (int i = 0; i < 2; ++i) {
                const int gm = m0 + wm + mi * 16 + gid + i * 8;
                const int b  = gm >> 11;
                const int s  = gm & 2047;
                #pragma unroll
                for (int ni = 0; ni < 4; ++ni) {
                    #pragma unroll
                    for (int j = 0; j < 2; ++j) {
                        const int gn = n0 + wn + ni * 8 + qid * 2 + j;
                        const int h  = gn >> 6, dd = gn & 63;
                        dst[(((size_t)(b * Hm + h) * DHm + dd) * Sm) + s] =
                            acc[mi][ni][i * 2 + j] + bias[gn];
                    }
                }
            }
        }
    } else {
        // V layout [bh][s][d]: float2 along d
        #pragma unroll
        for (int mi = 0; mi < 4; ++mi) {
            #pragma unroll
            for (int i = 0; i < 2; ++i) {
                const int gm = m0 + wm + mi * 16 + gid + i * 8;
                const int b  = gm >> 11;
                const int s  = gm & 2047;
                #pragma unroll
                for (int ni = 0; ni < 4; ++ni) {
                    const int gn0 = n0 + wn + ni * 8 + qid * 2;
                    const int h   = gn0 >> 6, dd0 = gn0 & 63;
                    float2 v;
                    v.x = acc[mi][ni][i * 2 + 0] + bias[gn0 + 0];
                    v.y = acc[mi][ni][i * 2 + 1] + bias[gn0 + 1];
                    *(float2*)&g_v[(((size_t)(b * Hm + h) * Sm + s) * DHm) + dd0] = v;
                }
            }
        }
    }
}

// ---------------------------------------------------------------------------
// Output projection + residual: y = ctx @ Wo^T + bo + x
// ---------------------------------------------------------------------------
__global__ void __launch_bounds__(256)
gemm_oproj_kernel(const float* __restrict__ ctx,
                  const float* __restrict__ Wo, const float* __restrict__ bo,
                  const float* __restrict__ x)
{
    float acc[4][4][4];
    #pragma unroll
    for (int mi = 0; mi < 4; ++mi)
        #pragma unroll
        for (int ni = 0; ni < 4; ++ni) {
            acc[mi][ni][0] = 0.f; acc[mi][ni][1] = 0.f;
            acc[mi][ni][2] = 0.f; acc[mi][ni][3] = 0.f;
        }

    gemm_main_tf32(ctx, Wo, acc);

    const int tid  = threadIdx.x;
    const int lane = tid & 31;
    const int warp = tid >> 5;
    const int wm   = (warp >> 2) * 64;
    const int wn   = (warp & 3) * 32;
    const int gid  = lane >> 2;
    const int qid  = lane & 3;
    const int m0   = blockIdx.y * 128;
    const int n0   = blockIdx.x * 128;

    #pragma unroll
    for (int mi = 0; mi < 4; ++mi) {
        #pragma unroll
        for (int i = 0; i < 2; ++i) {
            const int gm = m0 + wm + mi * 16 + gid + i * 8;
            #pragma unroll
            for (int ni = 0; ni < 4; ++ni) {
                const int gn0 = n0 + wn + ni * 8 + qid * 2;
                const size_t off = (size_t)gm * Dm + gn0;
                const float2 r = *(const float2*)&x[off];
                float2 v;
                v.x = acc[mi][ni][i * 2 + 0] + bo[gn0 + 0] + r.x;
                v.y = acc[mi][ni][i * 2 + 1] + bo[gn0 + 1] + r.y;
                *(float2*)&g_y[off] = v;
            }
        }
    }
}

// ---------------------------------------------------------------------------
// Causal flash attention, fp32 SIMT (unchanged from R1).
// ---------------------------------------------------------------------------
__global__ void __launch_bounds__(256)
attn_kernel(const float* __restrict__ Qg, const float* __restrict__ Kg,
            const float* __restrict__ Vg, float* __restrict__ ctx)
{
    __shared__ float Qt[64 * 64];
    __shared__ float KP[64 * 64];
    __shared__ float Vs[64 * 64];

    const int tid = threadIdx.x;
    const int ty  = tid >> 4;
    const int tx  = tid & 15;
    const int bh  = blockIdx.y;
    const int qb  = blockIdx.x;
    const int qi0 = qb * 64;

    const float* Qbh = Qg + (size_t)bh * DHm * Sm;
    const float* Kbh = Kg + (size_t)bh * DHm * Sm;
    const float* Vbh = Vg + (size_t)bh * Sm * DHm;

    #pragma unroll
    for (int idx = tid; idx < 1024; idx += 256) {
        const int d = idx >> 4, i4 = (idx & 15) * 4;
        *(float4*)&Qt[d * 64 + i4] = *(const float4*)&Qbh[(size_t)d * Sm + qi0 + i4];
    }

    float m_i[4], l_i[4], o[4][4];
    #pragma unroll
    for (int ii = 0; ii < 4; ++ii) {
        m_i[ii] = -1e30f;
        l_i[ii] = 0.f;
        o[ii][0] = o[ii][1] = o[ii][2] = o[ii][3] = 0.f;
    }
    __syncthreads();

    for (int kt = 0; kt <= qb; ++kt) {
        const int kj0 = kt * 64;
        #pragma unroll
        for (int idx = tid; idx < 1024; idx += 256) {
            const int d = idx >> 4, j4 = (idx & 15) * 4;
            *(float4*)&KP[d * 64 + j4] = *(const float4*)&Kbh[(size_t)d * Sm + kj0 + j4];
        }
        #pragma unroll
        for (int idx = tid; idx < 1024; idx += 256) {
            const int j = idx >> 4, d4 = (idx & 15) * 4;
            *(float4*)&Vs[j * 64 + d4] = *(const float4*)&Vbh[(size_t)(kj0 + j) * DHm + d4];
        }
        __syncthreads();

        float s[4][4];
        #pragma unroll
        for (int ii = 0; ii < 4; ++ii)
            s[ii][0] = s[ii][1] = s[ii][2] = s[ii][3] = 0.f;

        #pragma unroll 16
        for (int d = 0; d < 64; ++d) {
            float4 q4 = *(const float4*)&Qt[d * 64 + ty * 4];
            float4 k4 = *(const float4*)&KP[d * 64 + tx * 4];
            float qa[4] = {q4.x, q4.y, q4.z, q4.w};
            float ka[4] = {k4.x, k4.y, k4.z, k4.w};
            #pragma unroll
            for (int ii = 0; ii < 4; ++ii)
                #pragma unroll
                for (int jj = 0; jj < 4; ++jj)
                    s[ii][jj] += qa[ii] * ka[jj];
        }

        const bool diag = (kt == qb);
        #pragma unroll
        for (int ii = 0; ii < 4; ++ii)
            #pragma unroll
            for (int jj = 0; jj < 4; ++jj) {
                float v = s[ii][jj] * 0.125f;
                if (diag && (tx * 4 + jj > ty * 4 + ii)) v = -1e30f;
                s[ii][jj] = v;
            }

        float pr[4][4];
        #pragma unroll
        for (int ii = 0; ii < 4; ++ii) {
            float mx = fmaxf(fmaxf(s[ii][0], s[ii][1]), fmaxf(s[ii][2], s[ii][3]));
            #pragma unroll
            for (int off = 8; off > 0; off >>= 1)
                mx = fmaxf(mx, __shfl_xor_sync(0xffffffffu, mx, off));
            const float mn    = fmaxf(m_i[ii], mx);
            const float alpha = __expf(m_i[ii] - mn);
            m_i[ii] = mn;
            float ls = 0.f;
            #pragma unroll
            for (int jj = 0; jj < 4; ++jj) {
                const float p = __expf(s[ii][jj] - mn);
                pr[ii][jj] = p;
                ls += p;
            }
            #pragma unroll
            for (int off = 8; off > 0; off >>= 1)
                ls += __shfl_xor_sync(0xffffffffu, ls, off);
            l_i[ii] = l_i[ii] * alpha + ls;
            o[ii][0] *= alpha; o[ii][1] *= alpha; o[ii][2] *= alpha; o[ii][3] *= alpha;
        }

        __syncthreads();
        #pragma unroll
        for (int ii = 0; ii < 4; ++ii)
            *(float4*)&KP[(ty * 4 + ii) * 64 + tx * 4] =
                make_float4(pr[ii][0], pr[ii][1], pr[ii][2], pr[ii][3]);
        __syncthreads();

        #pragma unroll 16
        for (int j = 0; j < 64; ++j) {
            float4 v4 = *(const float4*)&Vs[j * 64 + tx * 4];
            #pragma unroll
            for (int ii = 0; ii < 4; ++ii) {
                const float p = KP[(ty * 4 + ii) * 64 + j];
                o[ii][0] += p * v4.x;
                o[ii][1] += p * v4.y;
                o[ii][2] += p * v4.z;
                o[ii][3] += p * v4.w;
            }
        }
        __syncthreads();
    }

    const int b = bh >> 4, h = bh & 15;
    #pragma unroll
    for (int ii = 0; ii < 4; ++ii) {
        const float inv  = 1.0f / l_i[ii];
        const int   srow = qi0 + ty * 4 + ii;
        float4 r = make_float4(o[ii][0] * inv, o[ii][1] * inv,
                               o[ii][2] * inv, o[ii][3] * inv);
        *(float4*)&ctx[((size_t)(b * Sm + srow)) * Dm + h * DHm + tx * 4] = r;
    }
}

// ---------------------------------------------------------------------------
// LayerNorm over last dim (1024). One block per row, 256 threads x 4 floats.
// ---------------------------------------------------------------------------
__global__ void __launch_bounds__(256)
ln_kernel(const float* __restrict__ y, const float* __restrict__ gam,
          const float* __restrict__ bet, float* __restrict__ out)
{
    __shared__ float red[2][8];
    const int row = blockIdx.x;
    const int tid = threadIdx.x;

    const float4 v = *(const float4*)&y[(size_t)row * Dm + tid * 4];
    float s  = v.x + v.y + v.z + v.w;
    float ss = v.x * v.x + v.y * v.y + v.z * v.z + v.w * v.w;

    #pragma unroll
    for (int off = 16; off > 0; off >>= 1) {
        s  += __shfl_xor_sync(0xffffffffu, s, off);
        ss += __shfl_xor_sync(0xffffffffu, ss, off);
    }
    const int wid = tid >> 5, lane = tid & 31;
    if (lane == 0) { red[0][wid] = s; red[1][wid] = ss; }
    __syncthreads();
    if (tid == 0) {
        float S = 0.f, SS = 0.f;
        #pragma unroll
        for (int w = 0; w < 8; ++w) { S += red[0][w]; SS += red[1][w]; }
        red[0][0] = S; red[1][0] = SS;
    }
    __syncthreads();

    const float mu   = red[0][0] * (1.0f / Dm);
    const float var  = red[1][0] * (1.0f / Dm) - mu * mu;
    const float rstd = rsqrtf(var + 1e-5f);

    const float4 g4 = *(const float4*)&gam[tid * 4];
    const float4 b4 = *(const float4*)&bet[tid * 4];
    float4 r;
    r.x = (v.x - mu) * rstd * g4.x + b4.x;
    r.y = (v.y - mu) * rstd * g4.y + b4.y;
    r.z = (v.z - mu) * rstd * g4.z + b4.z;
    r.w = (v.w - mu) * rstd * g4.w + b4.w;
    *(float4*)&out[(size_t)row * Dm + tid * 4] = r;
}

// ---------------------------------------------------------------------------
extern "C" void kernel_launch(void* const* d_in, const int* in_sizes, int n_in,
                              void* d_out, int out_size)
{
    const float* x    = (const float*)d_in[0];
    const float* Wq   = (const float*)d_in[1];
    const float* bq   = (const float*)d_in[2];
    const float* Wk   = (const float*)d_in[3];
    const float* bk   = (const float*)d_in[4];
    const float* Wv   = (const float*)d_in[5];
    const float* bv   = (const float*)d_in[6];
    const float* Wo   = (const float*)d_in[7];
    const float* bo   = (const float*)d_in[8];
    const float* ln_g = (const float*)d_in[9];
    const float* ln_b = (const float*)d_in[10];
    float* out = (float*)d_out;

    float *q_p, *k_p, *v_p, *ctx_p, *y_p;
    cudaGetSymbolAddress((void**)&q_p,   g_q);
    cudaGetSymbolAddress((void**)&k_p,   g_k);
    cudaGetSymbolAddress((void**)&v_p,   g_v);
    cudaGetSymbolAddress((void**)&ctx_p, g_ctx);
    cudaGetSymbolAddress((void**)&y_p,   g_y);

    gemm_qkv_kernel<<<dim3(8, 32, 3), 256>>>(x, Wq, bq, Wk, bk, Wv, bv);
    attn_kernel<<<dim3(32, 32), 256>>>(q_p, k_p, v_p, ctx_p);
    gemm_oproj_kernel<<<dim3(8, 32), 256>>>(ctx_p, Wo, bo, x);
    ln_kernel<<<4096, 256>>>(y_p, ln_g, ln_b, out);
}

// round 4
// speedup vs baseline: 2.4370x; 1.6471x over previous
#include <cuda_runtime.h>
#include <math.h>
#include <float.h>
#include <stdint.h>

#define Dm 1024
#define Sm 2048
#define Bm 2
#define Hm 16
#define DHm 64
#define BHm (Bm * Hm)

// Scratch (static device arrays; no allocations in kernel_launch)
__device__ float g_q[BHm * Sm * DHm];    // [b*H+h][s][d]
__device__ float g_k[BHm * Sm * DHm];    // [b*H+h][s][d]
__device__ float g_v[BHm * Sm * DHm];    // [b*H+h][s][d]
__device__ float g_ctx[Bm * Sm * Dm];    // [b][s][h*64+d]
__device__ float g_y[Bm * Sm * Dm];      // pre-LN residual sum

// ---------------------------------------------------------------------------
// tf32 helpers
// ---------------------------------------------------------------------------
__device__ __forceinline__ uint32_t f2tf(float x) {
    uint32_t r;
    asm("cvt.rna.tf32.f32 %0, %1;" : "=r"(r) : "f"(x));
    return r;
}

__device__ __forceinline__ void mma_tf32(float c[4], const uint32_t a[4], const uint32_t b[2]) {
    asm volatile(
        "mma.sync.aligned.m16n8k8.row.col.f32.tf32.tf32.f32 "
        "{%0,%1,%2,%3}, {%4,%5,%6,%7}, {%8,%9}, {%0,%1,%2,%3};"
        : "+f"(c[0]), "+f"(c[1]), "+f"(c[2]), "+f"(c[3])
        : "r"(a[0]), "r"(a[1]), "r"(a[2]), "r"(a[3]), "r"(b[0]), "r"(b[1]));
}

#define SSTR 20   // GEMM smem row stride in words

// ---------------------------------------------------------------------------
// tf32 GEMM mainloop: C[128x128] tile of A[M,K] @ W[N,K]^T, K=1024.
// 256 threads = 8 warps, each warp 64x32 (4 m-frags x 4 n-frags of m16n8k8).
// ---------------------------------------------------------------------------
__device__ __forceinline__ void gemm_main_tf32(const float* __restrict__ A,
                                               const float* __restrict__ Wt,
                                               float acc[4][4][4])
{
    __shared__ __align__(16) uint32_t As[128 * SSTR];
    __shared__ __align__(16) uint32_t Bs[128 * SSTR];

    const int tid  = threadIdx.x;
    const int lane = tid & 31;
    const int warp = tid >> 5;
    const int wm   = (warp >> 2) * 64;   // 0 or 64
    const int wn   = (warp & 3) * 32;    // 0,32,64,96
    const int gid  = lane >> 2;          // 0..7
    const int qid  = lane & 3;           // 0..3
    const int m0   = blockIdx.y * 128;
    const int n0   = blockIdx.x * 128;
    const int r0   = tid >> 2;           // 0..63
    const int k4   = (tid & 3) * 4;      // 0,4,8,12

    const float* Ap = A  + (size_t)(m0 + r0) * Dm + k4;
    const float* Bp = Wt + (size_t)(n0 + r0) * Dm + k4;

    float4 fa0 = *(const float4*)(Ap);
    float4 fa1 = *(const float4*)(Ap + 64 * Dm);
    float4 fb0 = *(const float4*)(Bp);
    float4 fb1 = *(const float4*)(Bp + 64 * Dm);

    for (int kt = 0; kt < 64; ++kt) {
        uint4 u;
        u.x = f2tf(fa0.x); u.y = f2tf(fa0.y); u.z = f2tf(fa0.z); u.w = f2tf(fa0.w);
        *(uint4*)&As[r0 * SSTR + k4] = u;
        u.x = f2tf(fa1.x); u.y = f2tf(fa1.y); u.z = f2tf(fa1.z); u.w = f2tf(fa1.w);
        *(uint4*)&As[(r0 + 64) * SSTR + k4] = u;
        u.x = f2tf(fb0.x); u.y = f2tf(fb0.y); u.z = f2tf(fb0.z); u.w = f2tf(fb0.w);
        *(uint4*)&Bs[r0 * SSTR + k4] = u;
        u.x = f2tf(fb1.x); u.y = f2tf(fb1.y); u.z = f2tf(fb1.z); u.w = f2tf(fb1.w);
        *(uint4*)&Bs[(r0 + 64) * SSTR + k4] = u;
        __syncthreads();

        if (kt < 63) {
            const float* Ap2 = Ap + (kt + 1) * 16;
            const float* Bp2 = Bp + (kt + 1) * 16;
            fa0 = *(const float4*)(Ap2);
            fa1 = *(const float4*)(Ap2 + 64 * Dm);
            fb0 = *(const float4*)(Bp2);
            fb1 = *(const float4*)(Bp2 + 64 * Dm);
        }

        #pragma unroll
        for (int ks = 0; ks < 2; ++ks) {
            const int kb = ks * 8 + qid;
            uint32_t a[4][4];
            uint32_t b[4][2];
            #pragma unroll
            for (int mi = 0; mi < 4; ++mi) {
                const uint32_t* p = &As[(wm + mi * 16 + gid) * SSTR + kb];
                a[mi][0] = p[0];
                a[mi][1] = p[8 * SSTR];
                a[mi][2] = p[4];
                a[mi][3] = p[8 * SSTR + 4];
            }
            #pragma unroll
            for (int ni = 0; ni < 4; ++ni) {
                const uint32_t* p = &Bs[(wn + ni * 8 + gid) * SSTR + kb];
                b[ni][0] = p[0];
                b[ni][1] = p[4];
            }
            #pragma unroll
            for (int mi = 0; mi < 4; ++mi)
                #pragma unroll
                for (int ni = 0; ni < 4; ++ni)
                    mma_tf32(acc[mi][ni], a[mi], b[ni]);
        }
        __syncthreads();
    }
}

// ---------------------------------------------------------------------------
// QKV projection. grid = (8, 32, 3): z selects Q/K/V. All stored [bh][s][d].
// ---------------------------------------------------------------------------
__global__ void __launch_bounds__(256)
gemm_qkv_kernel(const float* __restrict__ x,
                const float* __restrict__ Wq, const float* __restrict__ bq,
                const float* __restrict__ Wk, const float* __restrict__ bk,
                const float* __restrict__ Wv, const float* __restrict__ bv)
{
    const int z = blockIdx.z;
    const float* W    = (z == 0) ? Wq : (z == 1) ? Wk : Wv;
    const float* bias = (z == 0) ? bq : (z == 1) ? bk : bv;
    float* dst        = (z == 0) ? g_q : (z == 1) ? g_k : g_v;

    float acc[4][4][4];
    #pragma unroll
    for (int mi = 0; mi < 4; ++mi)
        #pragma unroll
        for (int ni = 0; ni < 4; ++ni) {
            acc[mi][ni][0] = 0.f; acc[mi][ni][1] = 0.f;
            acc[mi][ni][2] = 0.f; acc[mi][ni][3] = 0.f;
        }

    gemm_main_tf32(x, W, acc);

    const int tid  = threadIdx.x;
    const int lane = tid & 31;
    const int warp = tid >> 5;
    const int wm   = (warp >> 2) * 64;
    const int wn   = (warp & 3) * 32;
    const int gid  = lane >> 2;
    const int qid  = lane & 3;
    const int m0   = blockIdx.y * 128;
    const int n0   = blockIdx.x * 128;

    #pragma unroll
    for (int mi = 0; mi < 4; ++mi) {
        #pragma unroll
        for (int i = 0; i < 2; ++i) {
            const int gm = m0 + wm + mi * 16 + gid + i * 8;
            const int b  = gm >> 11;
            const int s  = gm & 2047;
            #pragma unroll
            for (int ni = 0; ni < 4; ++ni) {
                const int gn0 = n0 + wn + ni * 8 + qid * 2;
                const int h   = gn0 >> 6, dd0 = gn0 & 63;
                float2 v;
                v.x = acc[mi][ni][i * 2 + 0] + bias[gn0 + 0];
                v.y = acc[mi][ni][i * 2 + 1] + bias[gn0 + 1];
                *(float2*)&dst[(((size_t)(b * Hm + h) * Sm + s) * DHm) + dd0] = v;
            }
        }
    }
}

// ---------------------------------------------------------------------------
// Output projection + residual: y = ctx @ Wo^T + bo + x
// ---------------------------------------------------------------------------
__global__ void __launch_bounds__(256)
gemm_oproj_kernel(const float* __restrict__ ctx,
                  const float* __restrict__ Wo, const float* __restrict__ bo,
                  const float* __restrict__ x)
{
    float acc[4][4][4];
    #pragma unroll
    for (int mi = 0; mi < 4; ++mi)
        #pragma unroll
        for (int ni = 0; ni < 4; ++ni) {
            acc[mi][ni][0] = 0.f; acc[mi][ni][1] = 0.f;
            acc[mi][ni][2] = 0.f; acc[mi][ni][3] = 0.f;
        }

    gemm_main_tf32(ctx, Wo, acc);

    const int tid  = threadIdx.x;
    const int lane = tid & 31;
    const int warp = tid >> 5;
    const int wm   = (warp >> 2) * 64;
    const int wn   = (warp & 3) * 32;
    const int gid  = lane >> 2;
    const int qid  = lane & 3;
    const int m0   = blockIdx.y * 128;
    const int n0   = blockIdx.x * 128;

    #pragma unroll
    for (int mi = 0; mi < 4; ++mi) {
        #pragma unroll
        for (int i = 0; i < 2; ++i) {
            const int gm = m0 + wm + mi * 16 + gid + i * 8;
            #pragma unroll
            for (int ni = 0; ni < 4; ++ni) {
                const int gn0 = n0 + wn + ni * 8 + qid * 2;
                const size_t off = (size_t)gm * Dm + gn0;
                const float2 r = *(const float2*)&x[off];
                float2 v;
                v.x = acc[mi][ni][i * 2 + 0] + bo[gn0 + 0] + r.x;
                v.y = acc[mi][ni][i * 2 + 1] + bo[gn0 + 1] + r.y;
                *(float2*)&g_y[off] = v;
            }
        }
    }
}

// ---------------------------------------------------------------------------
// Causal flash attention, tf32 mma. grid = (S/64, B*H), 128 threads = 4 warps.
// Q,K,V in [bh][s][d]. Warp w owns q-rows w*16..w*16+15 (one m16 frag).
// smem: Ks[64][68] (K^T frags; reused for P), Vs[64][72]. 35KB.
// Accumulator frag (m16n8): thread(lane): rows g=lane>>2 (+8), cols 2q (+1).
// ---------------------------------------------------------------------------
#define LDK 68
#define LDV 72

__global__ void __launch_bounds__(128)
attn_kernel(const float* __restrict__ Qg, const float* __restrict__ Kg,
            const float* __restrict__ Vg, float* __restrict__ ctx)
{
    __shared__ __align__(16) uint32_t Ks[64 * LDK];   // K tile, then P tile
    __shared__ __align__(16) uint32_t Vs[64 * LDV];

    const int tid  = threadIdx.x;
    const int lane = tid & 31;
    const int warp = tid >> 5;
    const int g    = lane >> 2;   // 0..7
    const int q    = lane & 3;    // 0..3
    const int bh   = blockIdx.y;
    const int qb   = blockIdx.x;
    const int qi0  = qb * 64;
    const int wrow = warp * 16;

    const float* Qbh = Qg + (size_t)bh * Sm * DHm;
    const float* Kbh = Kg + (size_t)bh * Sm * DHm;
    const float* Vbh = Vg + (size_t)bh * Sm * DHm;

    // Q fragments (registers, whole block lifetime), pre-scaled by 1/sqrt(64)
    uint32_t qa[8][4];
    {
        const size_t r0 = (size_t)(qi0 + wrow + g) * DHm;
        const size_t r1 = r0 + 8 * DHm;
        #pragma unroll
        for (int kf = 0; kf < 8; ++kf) {
            const int d0 = kf * 8 + q;
            qa[kf][0] = f2tf(Qbh[r0 + d0]     * 0.125f);
            qa[kf][1] = f2tf(Qbh[r1 + d0]     * 0.125f);
            qa[kf][2] = f2tf(Qbh[r0 + d0 + 4] * 0.125f);
            qa[kf][3] = f2tf(Qbh[r1 + d0 + 4] * 0.125f);
        }
    }

    float m0 = -1e30f, m1 = -1e30f, l0 = 0.f, l1 = 0.f;
    float o[8][4];
    #pragma unroll
    for (int nf = 0; nf < 8; ++nf) {
        o[nf][0] = 0.f; o[nf][1] = 0.f; o[nf][2] = 0.f; o[nf][3] = 0.f;
    }

    for (int kt = 0; kt <= qb; ++kt) {
        const int kj0 = kt * 64;
        __syncthreads();   // previous iter's P/V reads complete

        // load K and V tiles (64x64 each), convert to tf32
        #pragma unroll
        for (int it = 0; it < 8; ++it) {
            const int idx = it * 128 + tid;          // 0..1023
            const int row = idx >> 4;
            const int c4  = (idx & 15) * 4;
            const float4 kv = *(const float4*)&Kbh[(size_t)(kj0 + row) * DHm + c4];
            Ks[row * LDK + c4 + 0] = f2tf(kv.x);
            Ks[row * LDK + c4 + 1] = f2tf(kv.y);
            Ks[row * LDK + c4 + 2] = f2tf(kv.z);
            Ks[row * LDK + c4 + 3] = f2tf(kv.w);
            const float4 vv = *(const float4*)&Vbh[(size_t)(kj0 + row) * DHm + c4];
            Vs[row * LDV + c4 + 0] = f2tf(vv.x);
            Vs[row * LDV + c4 + 1] = f2tf(vv.y);
            Vs[row * LDV + c4 + 2] = f2tf(vv.z);
            Vs[row * LDV + c4 + 3] = f2tf(vv.w);
        }
        __syncthreads();

        // S = Q K^T  (per warp: 16 x 64)
        float sacc[8][4];
        #pragma unroll
        for (int nf = 0; nf < 8; ++nf) {
            sacc[nf][0] = 0.f; sacc[nf][1] = 0.f; sacc[nf][2] = 0.f; sacc[nf][3] = 0.f;
        }
        #pragma unroll
        for (int kf = 0; kf < 8; ++kf) {
            #pragma unroll
            for (int nf = 0; nf < 8; ++nf) {
                uint32_t b[2];
                const uint32_t* p = &Ks[(nf * 8 + g) * LDK + kf * 8 + q];
                b[0] = p[0];
                b[1] = p[4];
                mma_tf32(sacc[nf], qa[kf], b);
            }
        }

        // causal mask on diagonal tile
        if (kt == qb) {
            const int r0l = wrow + g, r1l = r0l + 8;
            #pragma unroll
            for (int nf = 0; nf < 8; ++nf) {
                const int c = nf * 8 + 2 * q;
                if (c     > r0l) sacc[nf][0] = -1e30f;
                if (c + 1 > r0l) sacc[nf][1] = -1e30f;
                if (c     > r1l) sacc[nf][2] = -1e30f;
                if (c + 1 > r1l) sacc[nf][3] = -1e30f;
            }
        }

        // online softmax (rows live on 4 lanes: shfl over q)
        float mx0 = -1e30f, mx1 = -1e30f;
        #pragma unroll
        for (int nf = 0; nf < 8; ++nf) {
            mx0 = fmaxf(mx0, fmaxf(sacc[nf][0], sacc[nf][1]));
            mx1 = fmaxf(mx1, fmaxf(sacc[nf][2], sacc[nf][3]));
        }
        mx0 = fmaxf(mx0, __shfl_xor_sync(0xffffffffu, mx0, 1));
        mx0 = fmaxf(mx0, __shfl_xor_sync(0xffffffffu, mx0, 2));
        mx1 = fmaxf(mx1, __shfl_xor_sync(0xffffffffu, mx1, 1));
        mx1 = fmaxf(mx1, __shfl_xor_sync(0xffffffffu, mx1, 2));

        const float mn0 = fmaxf(m0, mx0);
        const float mn1 = fmaxf(m1, mx1);
        const float al0 = __expf(m0 - mn0);
        const float al1 = __expf(m1 - mn1);
        m0 = mn0; m1 = mn1;

        float rs0 = 0.f, rs1 = 0.f;
        #pragma unroll
        for (int nf = 0; nf < 8; ++nf) {
            sacc[nf][0] = __expf(sacc[nf][0] - mn0);
            sacc[nf][1] = __expf(sacc[nf][1] - mn0);
            sacc[nf][2] = __expf(sacc[nf][2] - mn1);
            sacc[nf][3] = __expf(sacc[nf][3] - mn1);
            rs0 += sacc[nf][0] + sacc[nf][1];
            rs1 += sacc[nf][2] + sacc[nf][3];
        }
        rs0 += __shfl_xor_sync(0xffffffffu, rs0, 1);
        rs0 += __shfl_xor_sync(0xffffffffu, rs0, 2);
        rs1 += __shfl_xor_sync(0xffffffffu, rs1, 1);
        rs1 += __shfl_xor_sync(0xffffffffu, rs1, 2);

        l0 = l0 * al0 + rs0;
        l1 = l1 * al1 + rs1;
        #pragma unroll
        for (int nf = 0; nf < 8; ++nf) {
            o[nf][0] *= al0; o[nf][1] *= al0;
            o[nf][2] *= al1; o[nf][3] *= al1;
        }

        __syncthreads();   // all warps done reading Ks -> reuse as P

        // store P (tf32) into Ks buffer; rows are warp-private
        {
            const int r0l = wrow + g, r1l = r0l + 8;
            #pragma unroll
            for (int nf = 0; nf < 8; ++nf) {
                const int c = nf * 8 + 2 * q;
                Ks[r0l * LDK + c]     = f2tf(sacc[nf][0]);
                Ks[r0l * LDK + c + 1] = f2tf(sacc[nf][1]);
                Ks[r1l * LDK + c]     = f2tf(sacc[nf][2]);
                Ks[r1l * LDK + c + 1] = f2tf(sacc[nf][3]);
            }
        }

        // O += P @ V  (per warp: 16 x 64, k = 64)
        #pragma unroll
        for (int kf = 0; kf < 8; ++kf) {
            uint32_t a[4];
            const int k0 = kf * 8 + q;
            a[0] = Ks[(wrow + g) * LDK + k0];
            a[1] = Ks[(wrow + g + 8) * LDK + k0];
            a[2] = Ks[(wrow + g) * LDK + k0 + 4];
            a[3] = Ks[(wrow + g + 8) * LDK + k0 + 4];
            #pragma unroll
            for (int nf = 0; nf < 8; ++nf) {
                uint32_t b[2];
                b[0] = Vs[k0 * LDV + nf * 8 + g];
                b[1] = Vs[(k0 + 4) * LDV + nf * 8 + g];
                mma_tf32(o[nf], a, b);
            }
        }
    }

    // epilogue: divide by l, write ctx [b][s][h*64+d]
    const int b = bh >> 4, h = bh & 15;
    const float inv0 = 1.0f / l0;
    const float inv1 = 1.0f / l1;
    const int s0 = qi0 + wrow + g;
    #pragma unroll
    for (int nf = 0; nf < 8; ++nf) {
        const int dd = h * DHm + nf * 8 + 2 * q;
        float2 v0 = make_float2(o[nf][0] * inv0, o[nf][1] * inv0);
        float2 v1 = make_float2(o[nf][2] * inv1, o[nf][3] * inv1);
        *(float2*)&ctx[((size_t)(b * Sm + s0)) * Dm + dd]     = v0;
        *(float2*)&ctx[((size_t)(b * Sm + s0 + 8)) * Dm + dd] = v1;
    }
}

// ---------------------------------------------------------------------------
// LayerNorm over last dim (1024). One block per row, 256 threads x 4 floats.
// ---------------------------------------------------------------------------
__global__ void __launch_bounds__(256)
ln_kernel(const float* __restrict__ y, const float* __restrict__ gam,
          const float* __restrict__ bet, float* __restrict__ out)
{
    __shared__ float red[2][8];
    const int row = blockIdx.x;
    const int tid = threadIdx.x;

    const float4 v = *(const float4*)&y[(size_t)row * Dm + tid * 4];
    float s  = v.x + v.y + v.z + v.w;
    float ss = v.x * v.x + v.y * v.y + v.z * v.z + v.w * v.w;

    #pragma unroll
    for (int off = 16; off > 0; off >>= 1) {
        s  += __shfl_xor_sync(0xffffffffu, s, off);
        ss += __shfl_xor_sync(0xffffffffu, ss, off);
    }
    const int wid = tid >> 5, lane = tid & 31;
    if (lane == 0) { red[0][wid] = s; red[1][wid] = ss; }
    __syncthreads();
    if (tid == 0) {
        float S = 0.f, SS = 0.f;
        #pragma unroll
        for (int w = 0; w < 8; ++w) { S += red[0][w]; SS += red[1][w]; }
        red[0][0] = S; red[1][0] = SS;
    }
    __syncthreads();

    const float mu   = red[0][0] * (1.0f / Dm);
    const float var  = red[1][0] * (1.0f / Dm) - mu * mu;
    const float rstd = rsqrtf(var + 1e-5f);

    const float4 g4 = *(const float4*)&gam[tid * 4];
    const float4 b4 = *(const float4*)&bet[tid * 4];
    float4 r;
    r.x = (v.x - mu) * rstd * g4.x + b4.x;
    r.y = (v.y - mu) * rstd * g4.y + b4.y;
    r.z = (v.z - mu) * rstd * g4.z + b4.z;
    r.w = (v.w - mu) * rstd * g4.w + b4.w;
    *(float4*)&out[(size_t)row * Dm + tid * 4] = r;
}

// ---------------------------------------------------------------------------
extern "C" void kernel_launch(void* const* d_in, const int* in_sizes, int n_in,
                              void* d_out, int out_size)
{
    const float* x    = (const float*)d_in[0];
    const float* Wq   = (const float*)d_in[1];
    const float* bq   = (const float*)d_in[2];
    const float* Wk   = (const float*)d_in[3];
    const float* bk   = (const float*)d_in[4];
    const float* Wv   = (const float*)d_in[5];
    const float* bv   = (const float*)d_in[6];
    const float* Wo   = (const float*)d_in[7];
    const float* bo   = (const float*)d_in[8];
    const float* ln_g = (const float*)d_in[9];
    const float* ln_b = (const float*)d_in[10];
    float* out = (float*)d_out;

    float *q_p, *k_p, *v_p, *ctx_p, *y_p;
    cudaGetSymbolAddress((void**)&q_p,   g_q);
    cudaGetSymbolAddress((void**)&k_p,   g_k);
    cudaGetSymbolAddress((void**)&v_p,   g_v);
    cudaGetSymbolAddress((void**)&ctx_p, g_ctx);
    cudaGetSymbolAddress((void**)&y_p,   g_y);

    gemm_qkv_kernel<<<dim3(8, 32, 3), 256>>>(x, Wq, bq, Wk, bk, Wv, bv);
    attn_kernel<<<dim3(32, 32), 128>>>(q_p, k_p, v_p, ctx_p);
    gemm_oproj_kernel<<<dim3(8, 32), 256>>>(ctx_p, Wo, bo, x);
    ln_kernel<<<4096, 256>>>(y_p, ln_g, ln_b, out);
}

// round 6
// speedup vs baseline: 3.4204x; 1.4035x over previous
#include <cuda_runtime.h>
#include <math.h>
#include <float.h>
#include <stdint.h>

#define Dm 1024
#define Sm 2048
#define Bm 2
#define Hm 16
#define DHm 64
#define BHm (Bm * Hm)

// Scratch (static device arrays; no allocations in kernel_launch)
__device__ float g_q[BHm * Sm * DHm];    // [b*H+h][s][d]
__device__ float g_k[BHm * Sm * DHm];    // [b*H+h][s][d]
__device__ float g_v[BHm * DHm * Sm];    // [b*H+h][d][s]  (transposed for PV mma)
__device__ float g_ctx[Bm * Sm * Dm];    // [b][s][h*64+d]
__device__ float g_y[Bm * Sm * Dm];      // pre-LN residual sum

// ---------------------------------------------------------------------------
// bf16 helpers
// ---------------------------------------------------------------------------
__device__ __forceinline__ uint32_t pack_bf16(float lo, float hi) {
    uint32_t r;
    asm("cvt.rn.bf16x2.f32 %0, %1, %2;" : "=r"(r) : "f"(hi), "f"(lo));
    return r;
}

__device__ __forceinline__ void mma_bf16(float c[4], const uint32_t a[4], const uint32_t b[2]) {
    asm volatile(
        "mma.sync.aligned.m16n8k16.row.col.f32.bf16.bf16.f32 "
        "{%0,%1,%2,%3}, {%4,%5,%6,%7}, {%8,%9}, {%0,%1,%2,%3};"
        : "+f"(c[0]), "+f"(c[1]), "+f"(c[2]), "+f"(c[3])
        : "r"(a[0]), "r"(a[1]), "r"(a[2]), "r"(a[3]), "r"(b[0]), "r"(b[1]));
}

#define SSTR 12   // GEMM smem row stride in words (8 used + 4 pad; 12g+q distinct mod 32)

// ---------------------------------------------------------------------------
// bf16 GEMM mainloop: C[128x128] tile of A[M,K] @ W[N,K]^T, K=1024, BK=16.
// 256 threads = 8 warps, each warp 64x32 (4 m-frags x 4 n-frags of m16n8k16).
// smem rows hold 16 bf16 = 8 uint32 (k-pairs packed in words).
// ---------------------------------------------------------------------------
__device__ __forceinline__ void gemm_main_bf16(const float* __restrict__ A,
                                               const float* __restrict__ Wt,
                                               float acc[4][4][4])
{
    __shared__ __align__(16) uint32_t As[128 * SSTR];
    __shared__ __align__(16) uint32_t Bs[128 * SSTR];

    const int tid  = threadIdx.x;
    const int lane = tid & 31;
    const int warp = tid >> 5;
    const int wm   = (warp >> 2) * 64;   // 0 or 64
    const int wn   = (warp & 3) * 32;    // 0,32,64,96
    const int g    = lane >> 2;          // 0..7
    const int q    = lane & 3;           // 0..3
    const int m0   = blockIdx.y * 128;
    const int n0   = blockIdx.x * 128;
    const int r0   = tid >> 1;           // 0..127
    const int kh   = (tid & 1) * 8;      // 0 or 8
    const int kw   = (tid & 1) * 4;      // word offset in smem row

    const float* Ap = A  + (size_t)(m0 + r0) * Dm + kh;
    const float* Bp = Wt + (size_t)(n0 + r0) * Dm + kh;

    float4 fa0 = *(const float4*)(Ap);
    float4 fa1 = *(const float4*)(Ap + 4);
    float4 fb0 = *(const float4*)(Bp);
    float4 fb1 = *(const float4*)(Bp + 4);

    for (int kt = 0; kt < 64; ++kt) {
        uint4 u;
        u.x = pack_bf16(fa0.x, fa0.y);
        u.y = pack_bf16(fa0.z, fa0.w);
        u.z = pack_bf16(fa1.x, fa1.y);
        u.w = pack_bf16(fa1.z, fa1.w);
        *(uint4*)&As[r0 * SSTR + kw] = u;
        u.x = pack_bf16(fb0.x, fb0.y);
        u.y = pack_bf16(fb0.z, fb0.w);
        u.z = pack_bf16(fb1.x, fb1.y);
        u.w = pack_bf16(fb1.z, fb1.w);
        *(uint4*)&Bs[r0 * SSTR + kw] = u;
        __syncthreads();

        if (kt < 63) {
            const float* Ap2 = Ap + (kt + 1) * 16;
            const float* Bp2 = Bp + (kt + 1) * 16;
            fa0 = *(const float4*)(Ap2);
            fa1 = *(const float4*)(Ap2 + 4);
            fb0 = *(const float4*)(Bp2);
            fb1 = *(const float4*)(Bp2 + 4);
        }

        uint32_t a[4][4];
        uint32_t b[4][2];
        #pragma unroll
        for (int mi = 0; mi < 4; ++mi) {
            const uint32_t* p = &As[(wm + mi * 16 + g) * SSTR + q];
            a[mi][0] = p[0];
            a[mi][1] = p[8 * SSTR];
            a[mi][2] = p[4];
            a[mi][3] = p[8 * SSTR + 4];
        }
        #pragma unroll
        for (int ni = 0; ni < 4; ++ni) {
            const uint32_t* p = &Bs[(wn + ni * 8 + g) * SSTR + q];
            b[ni][0] = p[0];
            b[ni][1] = p[4];
        }
        #pragma unroll
        for (int mi = 0; mi < 4; ++mi)
            #pragma unroll
            for (int ni = 0; ni < 4; ++ni)
                mma_bf16(acc[mi][ni], a[mi], b[ni]);
        __syncthreads();
    }
}

// ---------------------------------------------------------------------------
// QKV projection. grid = (8, 32, 3): z selects Q/K/V.
// Q,K stored [bh][s][d]; V stored [bh][d][s].
// ---------------------------------------------------------------------------
__global__ void __launch_bounds__(256)
gemm_qkv_kernel(const float* __restrict__ x,
                const float* __restrict__ Wq, const float* __restrict__ bq,
                const float* __restrict__ Wk, const float* __restrict__ bk,
                const float* __restrict__ Wv, const float* __restrict__ bv)
{
    const int z = blockIdx.z;
    const float* W    = (z == 0) ? Wq : (z == 1) ? Wk : Wv;
    const float* bias = (z == 0) ? bq : (z == 1) ? bk : bv;

    float acc[4][4][4];
    #pragma unroll
    for (int mi = 0; mi < 4; ++mi)
        #pragma unroll
        for (int ni = 0; ni < 4; ++ni) {
            acc[mi][ni][0] = 0.f; acc[mi][ni][1] = 0.f;
            acc[mi][ni][2] = 0.f; acc[mi][ni][3] = 0.f;
        }

    gemm_main_bf16(x, W, acc);

    const int tid  = threadIdx.x;
    const int lane = tid & 31;
    const int warp = tid >> 5;
    const int wm   = (warp >> 2) * 64;
    const int wn   = (warp & 3) * 32;
    const int g    = lane >> 2;
    const int q    = lane & 3;
    const int m0   = blockIdx.y * 128;
    const int n0   = blockIdx.x * 128;

    if (z < 2) {
        float* dst = (z == 0) ? g_q : g_k;
        #pragma unroll
        for (int mi = 0; mi < 4; ++mi) {
            #pragma unroll
            for (int i = 0; i < 2; ++i) {
                const int gm = m0 + wm + mi * 16 + g + i * 8;
                const int b  = gm >> 11;
                const int s  = gm & 2047;
                #pragma unroll
                for (int ni = 0; ni < 4; ++ni) {
                    const int gn0 = n0 + wn + ni * 8 + q * 2;
                    const int h   = gn0 >> 6, dd0 = gn0 & 63;
                    float2 v;
                    v.x = acc[mi][ni][i * 2 + 0] + bias[gn0 + 0];
                    v.y = acc[mi][ni][i * 2 + 1] + bias[gn0 + 1];
                    *(float2*)&dst[(((size_t)(b * Hm + h) * Sm + s) * DHm) + dd0] = v;
                }
            }
        }
    } else {
        // V: [bh][d][s] scatter (scalar stores, 32B-coherent per d-row)
        #pragma unroll
        for (int mi = 0; mi < 4; ++mi) {
            #pragma unroll
            for (int i = 0; i < 2; ++i) {
                const int gm = m0 + wm + mi * 16 + g + i * 8;
                const int b  = gm >> 11;
                const int s  = gm & 2047;
                #pragma unroll
                for (int ni = 0; ni < 4; ++ni) {
                    const int gn0 = n0 + wn + ni * 8 + q * 2;
                    const int h   = gn0 >> 6, dd0 = gn0 & 63;
                    const size_t base = ((size_t)(b * Hm + h) * DHm + dd0) * Sm + s;
                    g_v[base]      = acc[mi][ni][i * 2 + 0] + bias[gn0 + 0];
                    g_v[base + Sm] = acc[mi][ni][i * 2 + 1] + bias[gn0 + 1];
                }
            }
        }
    }
}

// ---------------------------------------------------------------------------
// Output projection + residual: y = ctx @ Wo^T + bo + x
// ---------------------------------------------------------------------------
__global__ void __launch_bounds__(256)
gemm_oproj_kernel(const float* __restrict__ ctx,
                  const float* __restrict__ Wo, const float* __restrict__ bo,
                  const float* __restrict__ x)
{
    float acc[4][4][4];
    #pragma unroll
    for (int mi = 0; mi < 4; ++mi)
        #pragma unroll
        for (int ni = 0; ni < 4; ++ni) {
            acc[mi][ni][0] = 0.f; acc[mi][ni][1] = 0.f;
            acc[mi][ni][2] = 0.f; acc[mi][ni][3] = 0.f;
        }

    gemm_main_bf16(ctx, Wo, acc);

    const int tid  = threadIdx.x;
    const int lane = tid & 31;
    const int warp = tid >> 5;
    const int wm   = (warp >> 2) * 64;
    const int wn   = (warp & 3) * 32;
    const int g    = lane >> 2;
    const int q    = lane & 3;
    const int m0   = blockIdx.y * 128;
    const int n0   = blockIdx.x * 128;

    #pragma unroll
    for (int mi = 0; mi < 4; ++mi) {
        #pragma unroll
        for (int i = 0; i < 2; ++i) {
            const int gm = m0 + wm + mi * 16 + g + i * 8;
            #pragma unroll
            for (int ni = 0; ni < 4; ++ni) {
                const int gn0 = n0 + wn + ni * 8 + q * 2;
                const size_t off = (size_t)gm * Dm + gn0;
                const float2 r = *(const float2*)&x[off];
                float2 v;
                v.x = acc[mi][ni][i * 2 + 0] + bo[gn0 + 0] + r.x;
                v.y = acc[mi][ni][i * 2 + 1] + bo[gn0 + 1] + r.y;
                *(float2*)&g_y[off] = v;
            }
        }
    }
}

// ---------------------------------------------------------------------------
// Causal flash attention, bf16 mma m16n8k16. grid = (S/64, B*H), 128 thr.
// Q,K in [bh][s][d]; V in [bh][d][s].
// smem: Ks[64][36] words (K d-pairs; reused for P j-pairs), Vt[64][36]
// (row=d, j-pairs). (36g+q) mod 32 = 4g+q -> conflict-free fragments.
// ---------------------------------------------------------------------------
#define ALD 36

__global__ void __launch_bounds__(128)
attn_kernel(const float* __restrict__ Qg, const float* __restrict__ Kg,
            const float* __restrict__ Vg, float* __restrict__ ctx)
{
    __shared__ __align__(16) uint32_t Ks[64 * ALD];   // K tile, then P tile
    __shared__ __align__(16) uint32_t Vt[64 * ALD];   // [d][j/2]

    const int tid  = threadIdx.x;
    const int lane = tid & 31;
    const int warp = tid >> 5;
    const int g    = lane >> 2;   // 0..7
    const int q    = lane & 3;    // 0..3
    const int bh   = blockIdx.y;
    const int qb   = blockIdx.x;
    const int qi0  = qb * 64;
    const int wrow = warp * 16;

    const float* Qbh = Qg + (size_t)bh * Sm * DHm;
    const float* Kbh = Kg + (size_t)bh * Sm * DHm;
    const float* Vbh = Vg + (size_t)bh * DHm * Sm;

    // Q fragments (registers, whole block), pre-scaled by 1/sqrt(64)
    uint32_t qa[4][4];
    {
        const size_t r0 = (size_t)(qi0 + wrow + g) * DHm;
        const size_t r1 = r0 + 8 * DHm;
        #pragma unroll
        for (int kf = 0; kf < 4; ++kf) {
            const int d0 = kf * 16 + 2 * q;
            float2 v;
            v = *(const float2*)&Qbh[r0 + d0];
            qa[kf][0] = pack_bf16(v.x * 0.125f, v.y * 0.125f);
            v = *(const float2*)&Qbh[r1 + d0];
            qa[kf][1] = pack_bf16(v.x * 0.125f, v.y * 0.125f);
            v = *(const float2*)&Qbh[r0 + d0 + 8];
            qa[kf][2] = pack_bf16(v.x * 0.125f, v.y * 0.125f);
            v = *(const float2*)&Qbh[r1 + d0 + 8];
            qa[kf][3] = pack_bf16(v.x * 0.125f, v.y * 0.125f);
        }
    }

    float m0 = -1e30f, m1 = -1e30f, l0 = 0.f, l1 = 0.f;
    float o[8][4];
    #pragma unroll
    for (int nf = 0; nf < 8; ++nf) {
        o[nf][0] = 0.f; o[nf][1] = 0.f; o[nf][2] = 0.f; o[nf][3] = 0.f;
    }

    for (int kt = 0; kt <= qb; ++kt) {
        const int kj0 = kt * 64;
        __syncthreads();   // previous iter's P/V reads complete

        // load K [j][d] and V [d][j] tiles, pack to bf16 pairs
        #pragma unroll
        for (int it = 0; it < 8; ++it) {
            const int idx = it * 128 + tid;          // 0..1023
            const int row = idx >> 4;                // K: j ; V: d
            const int c4  = (idx & 15) * 4;          // K: d ; V: j offset
            const float4 kv = *(const float4*)&Kbh[(size_t)(kj0 + row) * DHm + c4];
            uint2 w;
            w.x = pack_bf16(kv.x, kv.y);
            w.y = pack_bf16(kv.z, kv.w);
            *(uint2*)&Ks[row * ALD + (c4 >> 1)] = w;
            const float4 vv = *(const float4*)&Vbh[(size_t)row * Sm + kj0 + c4];
            w.x = pack_bf16(vv.x, vv.y);
            w.y = pack_bf16(vv.z, vv.w);
            *(uint2*)&Vt[row * ALD + (c4 >> 1)] = w;
        }
        __syncthreads();

        // S = Q K^T  (per warp: 16 x 64, k=64 over 4 k16 frags)
        float sacc[8][4];
        #pragma unroll
        for (int nf = 0; nf < 8; ++nf) {
            sacc[nf][0] = 0.f; sacc[nf][1] = 0.f; sacc[nf][2] = 0.f; sacc[nf][3] = 0.f;
        }
        #pragma unroll
        for (int kf = 0; kf < 4; ++kf) {
            #pragma unroll
            for (int nf = 0; nf < 8; ++nf) {
                uint32_t b[2];
                const uint32_t* p = &Ks[(nf * 8 + g) * ALD + kf * 8 + q];
                b[0] = p[0];
                b[1] = p[4];
                mma_bf16(sacc[nf], qa[kf], b);
            }
        }

        // causal mask on diagonal tile
        if (kt == qb) {
            const int r0l = wrow + g, r1l = r0l + 8;
            #pragma unroll
            for (int nf = 0; nf < 8; ++nf) {
                const int c = nf * 8 + 2 * q;
                if (c     > r0l) sacc[nf][0] = -1e30f;
                if (c + 1 > r0l) sacc[nf][1] = -1e30f;
                if (c     > r1l) sacc[nf][2] = -1e30f;
                if (c + 1 > r1l) sacc[nf][3] = -1e30f;
            }
        }

        // online softmax (rows live on 4 lanes: shfl over q)
        float mx0 = -1e30f, mx1 = -1e30f;
        #pragma unroll
        for (int nf = 0; nf < 8; ++nf) {
            mx0 = fmaxf(mx0, fmaxf(sacc[nf][0], sacc[nf][1]));
            mx1 = fmaxf(mx1, fmaxf(sacc[nf][2], sacc[nf][3]));
        }
        mx0 = fmaxf(mx0, __shfl_xor_sync(0xffffffffu, mx0, 1));
        mx0 = fmaxf(mx0, __shfl_xor_sync(0xffffffffu, mx0, 2));
        mx1 = fmaxf(mx1, __shfl_xor_sync(0xffffffffu, mx1, 1));
        mx1 = fmaxf(mx1, __shfl_xor_sync(0xffffffffu, mx1, 2));

        const float mn0 = fmaxf(m0, mx0);
        const float mn1 = fmaxf(m1, mx1);
        const float al0 = __expf(m0 - mn0);
        const float al1 = __expf(m1 - mn1);
        m0 = mn0; m1 = mn1;

        float rs0 = 0.f, rs1 = 0.f;
        #pragma unroll
        for (int nf = 0; nf < 8; ++nf) {
            sacc[nf][0] = __expf(sacc[nf][0] - mn0);
            sacc[nf][1] = __expf(sacc[nf][1] - mn0);
            sacc[nf][2] = __expf(sacc[nf][2] - mn1);
            sacc[nf][3] = __expf(sacc[nf][3] - mn1);
            rs0 += sacc[nf][0] + sacc[nf][1];
            rs1 += sacc[nf][2] + sacc[nf][3];
        }
        rs0 += __shfl_xor_sync(0xffffffffu, rs0, 1);
        rs0 += __shfl_xor_sync(0xffffffffu, rs0, 2);
        rs1 += __shfl_xor_sync(0xffffffffu, rs1, 1);
        rs1 += __shfl_xor_sync(0xffffffffu, rs1, 2);

        l0 = l0 * al0 + rs0;
        l1 = l1 * al1 + rs1;
        #pragma unroll
        for (int nf = 0; nf < 8; ++nf) {
            o[nf][0] *= al0; o[nf][1] *= al0;
            o[nf][2] *= al1; o[nf][3] *= al1;
        }

        __syncthreads();   // all warps done reading Ks -> reuse as P

        // store P (bf16 pairs of adjacent cols); rows are warp-private
        {
            const int r0l = wrow + g, r1l = r0l + 8;
            #pragma unroll
            for (int nf = 0; nf < 8; ++nf) {
                Ks[r0l * ALD + nf * 4 + q] = pack_bf16(sacc[nf][0], sacc[nf][1]);
                Ks[r1l * ALD + nf * 4 + q] = pack_bf16(sacc[nf][2], sacc[nf][3]);
            }
        }

        // O += P @ V  (per warp: 16 x 64, k=64 over 4 k16 frags)
        #pragma unroll
        for (int kf = 0; kf < 4; ++kf) {
            uint32_t a[4];
            const int kw = kf * 8 + q;
            a[0] = Ks[(wrow + g) * ALD + kw];
            a[1] = Ks[(wrow + g + 8) * ALD + kw];
            a[2] = Ks[(wrow + g) * ALD + kw + 4];
            a[3] = Ks[(wrow + g + 8) * ALD + kw + 4];
            #pragma unroll
            for (int nf = 0; nf < 8; ++nf) {
                uint32_t b[2];
                const uint32_t* p = &Vt[(nf * 8 + g) * ALD + kw];
                b[0] = p[0];
                b[1] = p[4];
                mma_bf16(o[nf], a, b);
            }
        }
    }

    // epilogue: divide by l, write ctx [b][s][h*64+d]
    const int b = bh >> 4, h = bh & 15;
    const float inv0 = 1.0f / l0;
    const float inv1 = 1.0f / l1;
    const int s0 = qi0 + wrow + g;
    #pragma unroll
    for (int nf = 0; nf < 8; ++nf) {
        const int dd = h * DHm + nf * 8 + 2 * q;
        float2 v0 = make_float2(o[nf][0] * inv0, o[nf][1] * inv0);
        float2 v1 = make_float2(o[nf][2] * inv1, o[nf][3] * inv1);
        *(float2*)&ctx[((size_t)(b * Sm + s0)) * Dm + dd]     = v0;
        *(float2*)&ctx[((size_t)(b * Sm + s0 + 8)) * Dm + dd] = v1;
    }
}

// ---------------------------------------------------------------------------
// LayerNorm over last dim (1024). One block per row, 256 threads x 4 floats.
// ---------------------------------------------------------------------------
__global__ void __launch_bounds__(256)
ln_kernel(const float* __restrict__ y, const float* __restrict__ gam,
          const float* __restrict__ bet, float* __restrict__ out)
{
    __shared__ float red[2][8];
    const int row = blockIdx.x;
    const int tid = threadIdx.x;

    const float4 v = *(const float4*)&y[(size_t)row * Dm + tid * 4];
    float s  = v.x + v.y + v.z + v.w;
    float ss = v.x * v.x + v.y * v.y + v.z * v.z + v.w * v.w;

    #pragma unroll
    for (int off = 16; off > 0; off >>= 1) {
        s  += __shfl_xor_sync(0xffffffffu, s, off);
        ss += __shfl_xor_sync(0xffffffffu, ss, off);
    }
    const int wid = tid >> 5, lane = tid & 31;
    if (lane == 0) { red[0][wid] = s; red[1][wid] = ss; }
    __syncthreads();
    if (tid == 0) {
        float S = 0.f, SS = 0.f;
        #pragma unroll
        for (int w = 0; w < 8; ++w) { S += red[0][w]; SS += red[1][w]; }
        red[0][0] = S; red[1][0] = SS;
    }
    __syncthreads();

    const float mu   = red[0][0] * (1.0f / Dm);
    const float var  = red[1][0] * (1.0f / Dm) - mu * mu;
    const float rstd = rsqrtf(var + 1e-5f);

    const float4 g4 = *(const float4*)&gam[tid * 4];
    const float4 b4 = *(const float4*)&bet[tid * 4];
    float4 r;
    r.x = (v.x - mu) * rstd * g4.x + b4.x;
    r.y = (v.y - mu) * rstd * g4.y + b4.y;
    r.z = (v.z - mu) * rstd * g4.z + b4.z;
    r.w = (v.w - mu) * rstd * g4.w + b4.w;
    *(float4*)&out[(size_t)row * Dm + tid * 4] = r;
}

// ---------------------------------------------------------------------------
extern "C" void kernel_launch(void* const* d_in, const int* in_sizes, int n_in,
                              void* d_out, int out_size)
{
    const float* x    = (const float*)d_in[0];
    const float* Wq   = (const float*)d_in[1];
    const float* bq   = (const float*)d_in[2];
    const float* Wk   = (const float*)d_in[3];
    const float* bk   = (const float*)d_in[4];
    const float* Wv   = (const float*)d_in[5];
    const float* bv   = (const float*)d_in[6];
    const float* Wo   = (const float*)d_in[7];
    const float* bo   = (const float*)d_in[8];
    const float* ln_g = (const float*)d_in[9];
    const float* ln_b = (const float*)d_in[10];
    float* out = (float*)d_out;

    float *q_p, *k_p, *v_p, *ctx_p, *y_p;
    cudaGetSymbolAddress((void**)&q_p,   g_q);
    cudaGetSymbolAddress((void**)&k_p,   g_k);
    cudaGetSymbolAddress((void**)&v_p,   g_v);
    cudaGetSymbolAddress((void**)&ctx_p, g_ctx);
    cudaGetSymbolAddress((void**)&y_p,   g_y);

    gemm_qkv_kernel<<<dim3(8, 32, 3), 256>>>(x, Wq, bq, Wk, bk, Wv, bv);
    attn_kernel<<<dim3(32, 32), 128>>>(q_p, k_p, v_p, ctx_p);
    gemm_oproj_kernel<<<dim3(8, 32), 256>>>(ctx_p, Wo, bo, x);
    ln_kernel<<<4096, 256>>>(y_p, ln_g, ln_b, out);
}

// round 8
// speedup vs baseline: 3.8338x; 1.1209x over previous
#include <cuda_runtime.h>
#include <math.h>
#include <float.h>
#include <stdint.h>

#define Dm 1024
#define Sm 2048
#define Bm 2
#define Hm 16
#define DHm 64
#define BHm (Bm * Hm)

// Scratch (static device arrays; no allocations in kernel_launch)
__device__ float g_q[BHm * Sm * DHm];    // [b*H+h][s][d]
__device__ float g_k[BHm * Sm * DHm];    // [b*H+h][s][d]
__device__ float g_v[BHm * DHm * Sm];    // [b*H+h][d][s]  (transposed for PV mma)
__device__ float g_ctx[Bm * Sm * Dm];    // [b][s][h*64+d]
__device__ float g_y[Bm * Sm * Dm];      // pre-LN residual sum

// ---------------------------------------------------------------------------
// bf16 / ldmatrix helpers
// ---------------------------------------------------------------------------
__device__ __forceinline__ uint32_t pack_bf16(float lo, float hi) {
    uint32_t r;
    asm("cvt.rn.bf16x2.f32 %0, %1, %2;" : "=r"(r) : "f"(hi), "f"(lo));
    return r;
}

__device__ __forceinline__ void mma_bf16(float c[4], const uint32_t a[4], const uint32_t b[2]) {
    asm volatile(
        "mma.sync.aligned.m16n8k16.row.col.f32.bf16.bf16.f32 "
        "{%0,%1,%2,%3}, {%4,%5,%6,%7}, {%8,%9}, {%0,%1,%2,%3};"
        : "+f"(c[0]), "+f"(c[1]), "+f"(c[2]), "+f"(c[3])
        : "r"(a[0]), "r"(a[1]), "r"(a[2]), "r"(a[3]), "r"(b[0]), "r"(b[1]));
}

__device__ __forceinline__ uint32_t cvta_s(const void* p) {
    return (uint32_t)__cvta_generic_to_shared(p);
}

#define LDSM4(R0, R1, R2, R3, ADDR) \
    asm volatile("ldmatrix.sync.aligned.m8n8.x4.shared.b16 {%0,%1,%2,%3}, [%4];" \
        : "=r"(R0), "=r"(R1), "=r"(R2), "=r"(R3) : "r"(ADDR))

#define SSTR 12   // GEMM smem row stride in words (48B: 8-row LDSM chunks cover all banks)

// ---------------------------------------------------------------------------
// bf16 GEMM mainloop: C[128x128] of A[M,K] @ W[N,K]^T, K=1024, BK=16.
// 256 threads = 8 warps, warp tile 64x32 (4 m-frags x 4 n-frags m16n8k16).
// Double-buffered smem, ldmatrix fragment loads, 1 sync per BK tile.
// ---------------------------------------------------------------------------
__device__ __forceinline__ void gemm_main_bf16(const float* __restrict__ A,
                                               const float* __restrict__ Wt,
                                               float acc[4][4][4])
{
    __shared__ __align__(16) uint32_t As[2][128 * SSTR];
    __shared__ __align__(16) uint32_t Bs[2][128 * SSTR];

    const int tid  = threadIdx.x;
    const int lane = tid & 31;
    const int warp = tid >> 5;
    const int wm   = (warp >> 2) * 64;   // 0 or 64
    const int wn   = (warp & 3) * 32;    // 0,32,64,96
    const int m0   = blockIdx.y * 128;
    const int n0   = blockIdx.x * 128;
    const int r0   = tid >> 1;           // 0..127
    const int kh   = (tid & 1) * 8;      // 0 or 8
    const int kw   = (tid & 1) * 4;      // word offset in smem row

    const float* Ap = A  + (size_t)(m0 + r0) * Dm + kh;
    const float* Bp = Wt + (size_t)(n0 + r0) * Dm + kh;

    // ldmatrix per-thread source addresses
    const int a_row  = wm + (lane & 15);
    const int a_word = (lane >> 4) * 4;
    const int b_row  = wn + (lane & 7) + ((lane & 16) >> 1);
    const int b_word = (lane & 8) ? 4 : 0;
    uint32_t aaddr[2], baddr[2];
    #pragma unroll
    for (int s = 0; s < 2; ++s) {
        aaddr[s] = cvta_s(&As[s][a_row * SSTR + a_word]);
        baddr[s] = cvta_s(&Bs[s][b_row * SSTR + b_word]);
    }

    // prologue: stage K-slab 0 into buffer 0
    float4 fa0 = *(const float4*)(Ap);
    float4 fa1 = *(const float4*)(Ap + 4);
    float4 fb0 = *(const float4*)(Bp);
    float4 fb1 = *(const float4*)(Bp + 4);
    {
        uint4 u;
        u.x = pack_bf16(fa0.x, fa0.y); u.y = pack_bf16(fa0.z, fa0.w);
        u.z = pack_bf16(fa1.x, fa1.y); u.w = pack_bf16(fa1.z, fa1.w);
        *(uint4*)&As[0][r0 * SSTR + kw] = u;
        u.x = pack_bf16(fb0.x, fb0.y); u.y = pack_bf16(fb0.z, fb0.w);
        u.z = pack_bf16(fb1.x, fb1.y); u.w = pack_bf16(fb1.z, fb1.w);
        *(uint4*)&Bs[0][r0 * SSTR + kw] = u;
    }
    __syncthreads();

    for (int kt = 0; kt < 64; ++kt) {
        const int cur = kt & 1;
        if (kt < 63) {
            const float* Ap2 = Ap + (kt + 1) * 16;
            const float* Bp2 = Bp + (kt + 1) * 16;
            fa0 = *(const float4*)(Ap2);
            fa1 = *(const float4*)(Ap2 + 4);
            fb0 = *(const float4*)(Bp2);
            fb1 = *(const float4*)(Bp2 + 4);
        }

        uint32_t a[4][4], b[4][2];
        #pragma unroll
        for (int mi = 0; mi < 4; ++mi)
            LDSM4(a[mi][0], a[mi][1], a[mi][2], a[mi][3],
                  aaddr[cur] + (mi * 16 * SSTR) * 4);
        #pragma unroll
        for (int n2 = 0; n2 < 2; ++n2)
            LDSM4(b[2 * n2][0], b[2 * n2][1], b[2 * n2 + 1][0], b[2 * n2 + 1][1],
                  baddr[cur] + (n2 * 16 * SSTR) * 4);

        #pragma unroll
        for (int mi = 0; mi < 4; ++mi)
            #pragma unroll
            for (int ni = 0; ni < 4; ++ni)
                mma_bf16(acc[mi][ni], a[mi], b[ni]);

        if (kt < 63) {
            const int nxt = cur ^ 1;
            uint4 u;
            u.x = pack_bf16(fa0.x, fa0.y); u.y = pack_bf16(fa0.z, fa0.w);
            u.z = pack_bf16(fa1.x, fa1.y); u.w = pack_bf16(fa1.z, fa1.w);
            *(uint4*)&As[nxt][r0 * SSTR + kw] = u;
            u.x = pack_bf16(fb0.x, fb0.y); u.y = pack_bf16(fb0.z, fb0.w);
            u.z = pack_bf16(fb1.x, fb1.y); u.w = pack_bf16(fb1.z, fb1.w);
            *(uint4*)&Bs[nxt][r0 * SSTR + kw] = u;
            __syncthreads();
        }
    }
}

// ---------------------------------------------------------------------------
// QKV projection. grid = (8, 32, 3): z selects Q/K/V.
// Q,K stored [bh][s][d]; V stored [bh][d][s].
// ---------------------------------------------------------------------------
__global__ void __launch_bounds__(256)
gemm_qkv_kernel(const float* __restrict__ x,
                const float* __restrict__ Wq, const float* __restrict__ bq,
                const float* __restrict__ Wk, const float* __restrict__ bk,
                const float* __restrict__ Wv, const float* __restrict__ bv)
{
    const int z = blockIdx.z;
    const float* W    = (z == 0) ? Wq : (z == 1) ? Wk : Wv;
    const float* bias = (z == 0) ? bq : (z == 1) ? bk : bv;

    float acc[4][4][4];
    #pragma unroll
    for (int mi = 0; mi < 4; ++mi)
        #pragma unroll
        for (int ni = 0; ni < 4; ++ni) {
            acc[mi][ni][0] = 0.f; acc[mi][ni][1] = 0.f;
            acc[mi][ni][2] = 0.f; acc[mi][ni][3] = 0.f;
        }

    gemm_main_bf16(x, W, acc);

    const int tid  = threadIdx.x;
    const int lane = tid & 31;
    const int warp = tid >> 5;
    const int wm   = (warp >> 2) * 64;
    const int wn   = (warp & 3) * 32;
    const int g    = lane >> 2;
    const int q    = lane & 3;
    const int m0   = blockIdx.y * 128;
    const int n0   = blockIdx.x * 128;

    if (z < 2) {
        float* dst = (z == 0) ? g_q : g_k;
        #pragma unroll
        for (int mi = 0; mi < 4; ++mi) {
            #pragma unroll
            for (int i = 0; i < 2; ++i) {
                const int gm = m0 + wm + mi * 16 + g + i * 8;
                const int b  = gm >> 11;
                const int s  = gm & 2047;
                #pragma unroll
                for (int ni = 0; ni < 4; ++ni) {
                    const int gn0 = n0 + wn + ni * 8 + q * 2;
                    const int h   = gn0 >> 6, dd0 = gn0 & 63;
                    float2 v;
                    v.x = acc[mi][ni][i * 2 + 0] + bias[gn0 + 0];
                    v.y = acc[mi][ni][i * 2 + 1] + bias[gn0 + 1];
                    *(float2*)&dst[(((size_t)(b * Hm + h) * Sm + s) * DHm) + dd0] = v;
                }
            }
        }
    } else {
        // V: [bh][d][s] scatter
        #pragma unroll
        for (int mi = 0; mi < 4; ++mi) {
            #pragma unroll
            for (int i = 0; i < 2; ++i) {
                const int gm = m0 + wm + mi * 16 + g + i * 8;
                const int b  = gm >> 11;
                const int s  = gm & 2047;
                #pragma unroll
                for (int ni = 0; ni < 4; ++ni) {
                    const int gn0 = n0 + wn + ni * 8 + q * 2;
                    const int h   = gn0 >> 6, dd0 = gn0 & 63;
                    const size_t base = ((size_t)(b * Hm + h) * DHm + dd0) * Sm + s;
                    g_v[base]      = acc[mi][ni][i * 2 + 0] + bias[gn0 + 0];
                    g_v[base + Sm] = acc[mi][ni][i * 2 + 1] + bias[gn0 + 1];
                }
            }
        }
    }
}

// ---------------------------------------------------------------------------
// Output projection + residual: y = ctx @ Wo^T + bo + x
// ---------------------------------------------------------------------------
__global__ void __launch_bounds__(256)
gemm_oproj_kernel(const float* __restrict__ ctx,
                  const float* __restrict__ Wo, const float* __restrict__ bo,
                  const float* __restrict__ x)
{
    float acc[4][4][4];
    #pragma unroll
    for (int mi = 0; mi < 4; ++mi)
        #pragma unroll
        for (int ni = 0; ni < 4; ++ni) {
            acc[mi][ni][0] = 0.f; acc[mi][ni][1] = 0.f;
            acc[mi][ni][2] = 0.f; acc[mi][ni][3] = 0.f;
        }

    gemm_main_bf16(ctx, Wo, acc);

    const int tid  = threadIdx.x;
    const int lane = tid & 31;
    const int warp = tid >> 5;
    const int wm   = (warp >> 2) * 64;
    const int wn   = (warp & 3) * 32;
    const int g    = lane >> 2;
    const int q    = lane & 3;
    const int m0   = blockIdx.y * 128;
    const int n0   = blockIdx.x * 128;

    #pragma unroll
    for (int mi = 0; mi < 4; ++mi) {
        #pragma unroll
        for (int i = 0; i < 2; ++i) {
            const int gm = m0 + wm + mi * 16 + g + i * 8;
            #pragma unroll
            for (int ni = 0; ni < 4; ++ni) {
                const int gn0 = n0 + wn + ni * 8 + q * 2;
                const size_t off = (size_t)gm * Dm + gn0;
                const float2 r = *(const float2*)&x[off];
                float2 v;
                v.x = acc[mi][ni][i * 2 + 0] + bo[gn0 + 0] + r.x;
                v.y = acc[mi][ni][i * 2 + 1] + bo[gn0 + 1] + r.y;
                *(float2*)&g_y[off] = v;
            }
        }
    }
}

// ---------------------------------------------------------------------------
// Causal flash attention, bf16 mma + ldmatrix. grid = (S/64, B*H), 128 thr.
// Q,K in [bh][s][d]; V in [bh][d][s].
// smem: Ks[64][36] words (K d-pairs; reused for P), Vt[64][36] (d rows, j-pairs).
// 36-word (144B) stride: 8-row LDSM chunks cover all 32 banks -> conflict-free.
// ---------------------------------------------------------------------------
#define ALD 36

__global__ void __launch_bounds__(128)
attn_kernel(const float* __restrict__ Qg, const float* __restrict__ Kg,
            const float* __restrict__ Vg, float* __restrict__ ctx)
{
    __shared__ __align__(16) uint32_t Ks[64 * ALD];   // K tile, then P tile
    __shared__ __align__(16) uint32_t Vt[64 * ALD];   // [d][j/2]

    const int tid  = threadIdx.x;
    const int lane = tid & 31;
    const int warp = tid >> 5;
    const int g    = lane >> 2;   // 0..7
    const int q    = lane & 3;    // 0..3
    const int bh   = blockIdx.y;
    const int qb   = blockIdx.x;
    const int qi0  = qb * 64;
    const int wrow = warp * 16;

    const float* Qbh = Qg + (size_t)bh * Sm * DHm;
    const float* Kbh = Kg + (size_t)bh * Sm * DHm;
    const float* Vbh = Vg + (size_t)bh * DHm * Sm;

    // ldmatrix source addresses
    const int fr_row = (lane & 7) + ((lane & 16) >> 1);
    const int fr_wrd = (lane & 8) ? 4 : 0;
    const uint32_t ks_b = cvta_s(&Ks[fr_row * ALD + fr_wrd]);
    const uint32_t vt_b = cvta_s(&Vt[fr_row * ALD + fr_wrd]);
    const uint32_t p_a  = cvta_s(&Ks[(wrow + (lane & 15)) * ALD + (lane >> 4) * 4]);

    // Q fragments (registers, whole block), pre-scaled by 1/sqrt(64)
    uint32_t qa[4][4];
    {
        const size_t r0 = (size_t)(qi0 + wrow + g) * DHm;
        const size_t r1 = r0 + 8 * DHm;
        #pragma unroll
        for (int kf = 0; kf < 4; ++kf) {
            const int d0 = kf * 16 + 2 * q;
            float2 v;
            v = *(const float2*)&Qbh[r0 + d0];
            qa[kf][0] = pack_bf16(v.x * 0.125f, v.y * 0.125f);
            v = *(const float2*)&Qbh[r1 + d0];
            qa[kf][1] = pack_bf16(v.x * 0.125f, v.y * 0.125f);
            v = *(const float2*)&Qbh[r0 + d0 + 8];
            qa[kf][2] = pack_bf16(v.x * 0.125f, v.y * 0.125f);
            v = *(const float2*)&Qbh[r1 + d0 + 8];
            qa[kf][3] = pack_bf16(v.x * 0.125f, v.y * 0.125f);
        }
    }

    float m0 = -1e30f, m1 = -1e30f, l0 = 0.f, l1 = 0.f;
    float o[8][4];
    #pragma unroll
    for (int nf = 0; nf < 8; ++nf) {
        o[nf][0] = 0.f; o[nf][1] = 0.f; o[nf][2] = 0.f; o[nf][3] = 0.f;
    }

    for (int kt = 0; kt <= qb; ++kt) {
        const int kj0 = kt * 64;
        __syncthreads();   // previous iter's P/V reads complete

        // load K [j][d] and V [d][j] tiles, pack to bf16 pairs
        #pragma unroll
        for (int it = 0; it < 8; ++it) {
            const int idx = it * 128 + tid;          // 0..1023
            const int row = idx >> 4;                // K: j ; V: d
            const int c4  = (idx & 15) * 4;          // K: d ; V: j offset
            const float4 kv = *(const float4*)&Kbh[(size_t)(kj0 + row) * DHm + c4];
            uint2 w;
            w.x = pack_bf16(kv.x, kv.y);
            w.y = pack_bf16(kv.z, kv.w);
            *(uint2*)&Ks[row * ALD + (c4 >> 1)] = w;
            const float4 vv = *(const float4*)&Vbh[(size_t)row * Sm + kj0 + c4];
            w.x = pack_bf16(vv.x, vv.y);
            w.y = pack_bf16(vv.z, vv.w);
            *(uint2*)&Vt[row * ALD + (c4 >> 1)] = w;
        }
        __syncthreads();

        // S = Q K^T  (per warp: 16 x 64, k=64 over 4 k16 frags; ldmatrix B)
        float sacc[8][4];
        #pragma unroll
        for (int nf = 0; nf < 8; ++nf) {
            sacc[nf][0] = 0.f; sacc[nf][1] = 0.f; sacc[nf][2] = 0.f; sacc[nf][3] = 0.f;
        }
        #pragma unroll
        for (int kf = 0; kf < 4; ++kf) {
            #pragma unroll
            for (int n2 = 0; n2 < 4; ++n2) {
                uint32_t b4[4];
                LDSM4(b4[0], b4[1], b4[2], b4[3],
                      ks_b + (n2 * 16 * ALD + kf * 8) * 4);
                mma_bf16(sacc[2 * n2],     qa[kf], b4);
                mma_bf16(sacc[2 * n2 + 1], qa[kf], b4 + 2);
            }
        }

        // causal mask on diagonal tile
        if (kt == qb) {
            const int r0l = wrow + g, r1l = r0l + 8;
            #pragma unroll
            for (int nf = 0; nf < 8; ++nf) {
                const int c = nf * 8 + 2 * q;
                if (c     > r0l) sacc[nf][0] = -1e30f;
                if (c + 1 > r0l) sacc[nf][1] = -1e30f;
                if (c     > r1l) sacc[nf][2] = -1e30f;
                if (c + 1 > r1l) sacc[nf][3] = -1e30f;
            }
        }

        // online softmax (rows live on 4 lanes: shfl over q)
        float mx0 = -1e30f, mx1 = -1e30f;
        #pragma unroll
        for (int nf = 0; nf < 8; ++nf) {
            mx0 = fmaxf(mx0, fmaxf(sacc[nf][0], sacc[nf][1]));
            mx1 = fmaxf(mx1, fmaxf(sacc[nf][2], sacc[nf][3]));
        }
        mx0 = fmaxf(mx0, __shfl_xor_sync(0xffffffffu, mx0, 1));
        mx0 = fmaxf(mx0, __shfl_xor_sync(0xffffffffu, mx0, 2));
        mx1 = fmaxf(mx1, __shfl_xor_sync(0xffffffffu, mx1, 1));
        mx1 = fmaxf(mx1, __shfl_xor_sync(0xffffffffu, mx1, 2));

        const float mn0 = fmaxf(m0, mx0);
        const float mn1 = fmaxf(m1, mx1);
        const float al0 = __expf(m0 - mn0);
        const float al1 = __expf(m1 - mn1);
        m0 = mn0; m1 = mn1;

        float rs0 = 0.f, rs1 = 0.f;
        #pragma unroll
        for (int nf = 0; nf < 8; ++nf) {
            sacc[nf][0] = __expf(sacc[nf][0] - mn0);
            sacc[nf][1] = __expf(sacc[nf][1] - mn0);
            sacc[nf][2] = __expf(sacc[nf][2] - mn1);
            sacc[nf][3] = __expf(sacc[nf][3] - mn1);
            rs0 += sacc[nf][0] + sacc[nf][1];
            rs1 += sacc[nf][2] + sacc[nf][3];
        }
        rs0 += __shfl_xor_sync(0xffffffffu, rs0, 1);
        rs0 += __shfl_xor_sync(0xffffffffu, rs0, 2);
        rs1 += __shfl_xor_sync(0xffffffffu, rs1, 1);
        rs1 += __shfl_xor_sync(0xffffffffu, rs1, 2);

        l0 = l0 * al0 + rs0;
        l1 = l1 * al1 + rs1;
        #pragma unroll
        for (int nf = 0; nf < 8; ++nf) {
            o[nf][0] *= al0; o[nf][1] *= al0;
            o[nf][2] *= al1; o[nf][3] *= al1;
        }

        __syncthreads();   // all warps done reading Ks -> reuse as P

        // store P (bf16 pairs of adjacent cols); rows are warp-private
        {
            const int r0l = wrow + g, r1l = r0l + 8;
            #pragma unroll
            for (int nf = 0; nf < 8; ++nf) {
                Ks[r0l * ALD + nf * 4 + q] = pack_bf16(sacc[nf][0], sacc[nf][1]);
                Ks[r1l * ALD + nf * 4 + q] = pack_bf16(sacc[nf][2], sacc[nf][3]);
            }
        }
        __syncwarp();

        // O += P @ V  (per warp: 16 x 64, ldmatrix A from P rows + B from Vt)
        #pragma unroll
        for (int kf = 0; kf < 4; ++kf) {
            uint32_t a4[4];
            LDSM4(a4[0], a4[1], a4[2], a4[3], p_a + (kf * 8) * 4);
            #pragma unroll
            for (int n2 = 0; n2 < 4; ++n2) {
                uint32_t b4[4];
                LDSM4(b4[0], b4[1], b4[2], b4[3],
                      vt_b + (n2 * 16 * ALD + kf * 8) * 4);
                mma_bf16(o[2 * n2],     a4, b4);
                mma_bf16(o[2 * n2 + 1], a4, b4 + 2);
            }
        }
    }

    // epilogue: divide by l, write ctx [b][s][h*64+d]
    const int b = bh >> 4, h = bh & 15;
    const float inv0 = 1.0f / l0;
    const float inv1 = 1.0f / l1;
    const int s0 = qi0 + wrow + g;
    #pragma unroll
    for (int nf = 0; nf < 8; ++nf) {
        const int dd = h * DHm + nf * 8 + 2 * q;
        float2 v0 = make_float2(o[nf][0] * inv0, o[nf][1] * inv0);
        float2 v1 = make_float2(o[nf][2] * inv1, o[nf][3] * inv1);
        *(float2*)&ctx[((size_t)(b * Sm + s0)) * Dm + dd]     = v0;
        *(float2*)&ctx[((size_t)(b * Sm + s0 + 8)) * Dm + dd] = v1;
    }
}

// ---------------------------------------------------------------------------
// LayerNorm over last dim (1024). One block per row, 256 threads x 4 floats.
// ---------------------------------------------------------------------------
__global__ void __launch_bounds__(256)
ln_kernel(const float* __restrict__ y, const float* __restrict__ gam,
          const float* __restrict__ bet, float* __restrict__ out)
{
    __shared__ float red[2][8];
    const int row = blockIdx.x;
    const int tid = threadIdx.x;

    const float4 v = *(const float4*)&y[(size_t)row * Dm + tid * 4];
    float s  = v.x + v.y + v.z + v.w;
    float ss = v.x * v.x + v.y * v.y + v.z * v.z + v.w * v.w;

    #pragma unroll
    for (int off = 16; off > 0; off >>= 1) {
        s  += __shfl_xor_sync(0xffffffffu, s, off);
        ss += __shfl_xor_sync(0xffffffffu, ss, off);
    }
    const int wid = tid >> 5, lane = tid & 31;
    if (lane == 0) { red[0][wid] = s; red[1][wid] = ss; }
    __syncthreads();
    if (tid == 0) {
        float S = 0.f, SS = 0.f;
        #pragma unroll
        for (int w = 0; w < 8; ++w) { S += red[0][w]; SS += red[1][w]; }
        red[0][0] = S; red[1][0] = SS;
    }
    __syncthreads();

    const float mu   = red[0][0] * (1.0f / Dm);
    const float var  = red[1][0] * (1.0f / Dm) - mu * mu;
    const float rstd = rsqrtf(var + 1e-5f);

    const float4 g4 = *(const float4*)&gam[tid * 4];
    const float4 b4 = *(const float4*)&bet[tid * 4];
    float4 r;
    r.x = (v.x - mu) * rstd * g4.x + b4.x;
    r.y = (v.y - mu) * rstd * g4.y + b4.y;
    r.z = (v.z - mu) * rstd * g4.z + b4.z;
    r.w = (v.w - mu) * rstd * g4.w + b4.w;
    *(float4*)&out[(size_t)row * Dm + tid * 4] = r;
}

// ---------------------------------------------------------------------------
extern "C" void kernel_launch(void* const* d_in, const int* in_sizes, int n_in,
                              void* d_out, int out_size)
{
    const float* x    = (const float*)d_in[0];
    const float* Wq   = (const float*)d_in[1];
    const float* bq   = (const float*)d_in[2];
    const float* Wk   = (const float*)d_in[3];
    const float* bk   = (const float*)d_in[4];
    const float* Wv   = (const float*)d_in[5];
    const float* bv   = (const float*)d_in[6];
    const float* Wo   = (const float*)d_in[7];
    const float* bo   = (const float*)d_in[8];
    const float* ln_g = (const float*)d_in[9];
    const float* ln_b = (const float*)d_in[10];
    float* out = (float*)d_out;

    float *q_p, *k_p, *v_p, *ctx_p, *y_p;
    cudaGetSymbolAddress((void**)&q_p,   g_q);
    cudaGetSymbolAddress((void**)&k_p,   g_k);
    cudaGetSymbolAddress((void**)&v_p,   g_v);
    cudaGetSymbolAddress((void**)&ctx_p, g_ctx);
    cudaGetSymbolAddress((void**)&y_p,   g_y);

    gemm_qkv_kernel<<<dim3(8, 32, 3), 256>>>(x, Wq, bq, Wk, bk, Wv, bv);
    attn_kernel<<<dim3(32, 32), 128>>>(q_p, k_p, v_p, ctx_p);
    gemm_oproj_kernel<<<dim3(8, 32), 256>>>(ctx_p, Wo, bo, x);
    ln_kernel<<<4096, 256>>>(y_p, ln_g, ln_b, out);
}

// round 9
// speedup vs baseline: 4.0489x; 1.0561x over previous
#include <cuda_runtime.h>
#include <cuda_bf16.h>
#include <math.h>
#include <float.h>
#include <stdint.h>

#define Dm 1024
#define Sm 2048
#define Bm 2
#define Hm 16
#define DHm 64
#define BHm (Bm * Hm)

// Scratch (static device arrays; no allocations in kernel_launch)
__device__ __nv_bfloat16 g_xb[Bm * Sm * Dm];      // x in bf16
__device__ __nv_bfloat16 g_wqb[Dm * Dm];
__device__ __nv_bfloat16 g_wkb[Dm * Dm];
__device__ __nv_bfloat16 g_wvb[Dm * Dm];
__device__ __nv_bfloat16 g_wob[Dm * Dm];
__device__ __nv_bfloat16 g_q[BHm * Sm * DHm];     // [bh][s][d], pre-scaled by 1/8
__device__ __nv_bfloat16 g_k[BHm * Sm * DHm];     // [bh][s][d]
__device__ __nv_bfloat16 g_v[BHm * DHm * Sm];     // [bh][d][s]
__device__ __nv_bfloat16 g_ctx[Bm * Sm * Dm];     // [b][s][h*64+d]
__device__ float g_y[Bm * Sm * Dm];               // pre-LN residual sum (fp32)

// ---------------------------------------------------------------------------
// helpers
// ---------------------------------------------------------------------------
__device__ __forceinline__ uint32_t pack_bf16(float lo, float hi) {
    uint32_t r;
    asm("cvt.rn.bf16x2.f32 %0, %1, %2;" : "=r"(r) : "f"(hi), "f"(lo));
    return r;
}

__device__ __forceinline__ void mma_bf16(float c[4], const uint32_t a[4], const uint32_t b[2]) {
    asm volatile(
        "mma.sync.aligned.m16n8k16.row.col.f32.bf16.bf16.f32 "
        "{%0,%1,%2,%3}, {%4,%5,%6,%7}, {%8,%9}, {%0,%1,%2,%3};"
        : "+f"(c[0]), "+f"(c[1]), "+f"(c[2]), "+f"(c[3])
        : "r"(a[0]), "r"(a[1]), "r"(a[2]), "r"(a[3]), "r"(b[0]), "r"(b[1]));
}

__device__ __forceinline__ uint32_t cvta_s(const void* p) {
    return (uint32_t)__cvta_generic_to_shared(p);
}

#define LDSM4(R0, R1, R2, R3, ADDR) \
    asm volatile("ldmatrix.sync.aligned.m8n8.x4.shared.b16 {%0,%1,%2,%3}, [%4];" \
        : "=r"(R0), "=r"(R1), "=r"(R2), "=r"(R3) : "r"(ADDR))

#define CP16(DST, SRC) \
    asm volatile("cp.async.cg.shared.global [%0], [%1], 16;" :: "r"(DST), "l"(SRC))
#define CP_COMMIT() asm volatile("cp.async.commit_group;")
#define CP_WAIT0()  asm volatile("cp.async.wait_group 0;")

// ---------------------------------------------------------------------------
// fp32 -> bf16 bulk convert
// ---------------------------------------------------------------------------
__global__ void __launch_bounds__(256)
to_bf16_kernel(const float* __restrict__ src, __nv_bfloat16* __restrict__ dst, int n4)
{
    const int i = blockIdx.x * blockDim.x + threadIdx.x;
    if (i < n4) {
        const float4 v = ((const float4*)src)[i];
        uint2 w;
        w.x = pack_bf16(v.x, v.y);
        w.y = pack_bf16(v.z, v.w);
        ((uint2*)dst)[i] = w;
    }
}

#define SSTR 12   // GEMM smem row stride in words (48B)

// ---------------------------------------------------------------------------
// bf16 GEMM mainloop: C[128x128] of A[M,K] @ W[N,K]^T, K=1024, BK=16.
// Inputs bf16; cp.async 16B global->smem, double buffer, ldmatrix, 1 sync/tile.
// ---------------------------------------------------------------------------
__device__ __forceinline__ void gemm_main_bf16(const __nv_bfloat16* __restrict__ A,
                                               const __nv_bfloat16* __restrict__ Wt,
                                               float acc[4][4][4])
{
    __shared__ __align__(16) uint32_t As[2][128 * SSTR];
    __shared__ __align__(16) uint32_t Bs[2][128 * SSTR];

    const int tid  = threadIdx.x;
    const int lane = tid & 31;
    const int warp = tid >> 5;
    const int wm   = (warp >> 2) * 64;
    const int wn   = (warp & 3) * 32;
    const int m0   = blockIdx.y * 128;
    const int n0   = blockIdx.x * 128;
    const int r0   = tid >> 1;           // 0..127
    const int kh   = (tid & 1) * 8;      // element offset 0 or 8
    const int kw   = (tid & 1) * 4;      // word offset in smem row

    const __nv_bfloat16* Ap = A  + (size_t)(m0 + r0) * Dm + kh;
    const __nv_bfloat16* Bp = Wt + (size_t)(n0 + r0) * Dm + kh;

    uint32_t sA[2], sB[2];
    #pragma unroll
    for (int s = 0; s < 2; ++s) {
        sA[s] = cvta_s(&As[s][r0 * SSTR + kw]);
        sB[s] = cvta_s(&Bs[s][r0 * SSTR + kw]);
    }

    // ldmatrix per-thread source addresses
    const int a_row  = wm + (lane & 15);
    const int a_word = (lane >> 4) * 4;
    const int b_row  = wn + (lane & 7) + ((lane & 16) >> 1);
    const int b_word = (lane & 8) ? 4 : 0;
    uint32_t aaddr[2], baddr[2];
    #pragma unroll
    for (int s = 0; s < 2; ++s) {
        aaddr[s] = cvta_s(&As[s][a_row * SSTR + a_word]);
        baddr[s] = cvta_s(&Bs[s][b_row * SSTR + b_word]);
    }

    // prologue: stage K-slab 0
    CP16(sA[0], Ap);
    CP16(sB[0], Bp);
    CP_COMMIT();
    CP_WAIT0();
    __syncthreads();

    for (int kt = 0; kt < 64; ++kt) {
        const int cur = kt & 1;
        if (kt < 63) {
            const int nxt = cur ^ 1;
            CP16(sA[nxt], Ap + (kt + 1) * 16);
            CP16(sB[nxt], Bp + (kt + 1) * 16);
            CP_COMMIT();
        }

        uint32_t a[4][4], b[4][2];
        #pragma unroll
        for (int mi = 0; mi < 4; ++mi)
            LDSM4(a[mi][0], a[mi][1], a[mi][2], a[mi][3],
                  aaddr[cur] + (mi * 16 * SSTR) * 4);
        #pragma unroll
        for (int n2 = 0; n2 < 2; ++n2)
            LDSM4(b[2 * n2][0], b[2 * n2][1], b[2 * n2 + 1][0], b[2 * n2 + 1][1],
                  baddr[cur] + (n2 * 16 * SSTR) * 4);

        #pragma unroll
        for (int mi = 0; mi < 4; ++mi)
            #pragma unroll
            for (int ni = 0; ni < 4; ++ni)
                mma_bf16(acc[mi][ni], a[mi], b[ni]);

        if (kt < 63) {
            CP_WAIT0();
            __syncthreads();
        }
    }
}

// ---------------------------------------------------------------------------
// QKV projection. grid = (8, 32, 3): z selects Q/K/V.
// Q (scaled 1/8), K stored bf16 [bh][s][d]; V stored bf16 [bh][d][s].
// ---------------------------------------------------------------------------
__global__ void __launch_bounds__(256)
gemm_qkv_kernel(const float* __restrict__ bq, const float* __restrict__ bk,
                const float* __restrict__ bv)
{
    const int z = blockIdx.z;
    const __nv_bfloat16* W = (z == 0) ? g_wqb : (z == 1) ? g_wkb : g_wvb;
    const float* bias      = (z == 0) ? bq : (z == 1) ? bk : bv;

    float acc[4][4][4];
    #pragma unroll
    for (int mi = 0; mi < 4; ++mi)
        #pragma unroll
        for (int ni = 0; ni < 4; ++ni) {
            acc[mi][ni][0] = 0.f; acc[mi][ni][1] = 0.f;
            acc[mi][ni][2] = 0.f; acc[mi][ni][3] = 0.f;
        }

    gemm_main_bf16(g_xb, W, acc);

    const int tid  = threadIdx.x;
    const int lane = tid & 31;
    const int warp = tid >> 5;
    const int wm   = (warp >> 2) * 64;
    const int wn   = (warp & 3) * 32;
    const int g    = lane >> 2;
    const int q    = lane & 3;
    const int m0   = blockIdx.y * 128;
    const int n0   = blockIdx.x * 128;

    if (z < 2) {
        __nv_bfloat16* dst = (z == 0) ? g_q : g_k;
        const float sc = (z == 0) ? 0.125f : 1.0f;
        #pragma unroll
        for (int mi = 0; mi < 4; ++mi) {
            #pragma unroll
            for (int i = 0; i < 2; ++i) {
                const int gm = m0 + wm + mi * 16 + g + i * 8;
                const int b  = gm >> 11;
                const int s  = gm & 2047;
                #pragma unroll
                for (int ni = 0; ni < 4; ++ni) {
                    const int gn0 = n0 + wn + ni * 8 + q * 2;
                    const int h   = gn0 >> 6, dd0 = gn0 & 63;
                    const uint32_t w = pack_bf16((acc[mi][ni][i * 2 + 0] + bias[gn0 + 0]) * sc,
                                                 (acc[mi][ni][i * 2 + 1] + bias[gn0 + 1]) * sc);
                    *(uint32_t*)&dst[(((size_t)(b * Hm + h) * Sm + s) * DHm) + dd0] = w;
                }
            }
        }
    } else {
        // V: [bh][d][s] scatter (2B stores)
        #pragma unroll
        for (int mi = 0; mi < 4; ++mi) {
            #pragma unroll
            for (int i = 0; i < 2; ++i) {
                const int gm = m0 + wm + mi * 16 + g + i * 8;
                const int b  = gm >> 11;
                const int s  = gm & 2047;
                #pragma unroll
                for (int ni = 0; ni < 4; ++ni) {
                    const int gn0 = n0 + wn + ni * 8 + q * 2;
                    const int h   = gn0 >> 6, dd0 = gn0 & 63;
                    const size_t base = ((size_t)(b * Hm + h) * DHm + dd0) * Sm + s;
                    g_v[base]      = __float2bfloat16_rn(acc[mi][ni][i * 2 + 0] + bias[gn0 + 0]);
                    g_v[base + Sm] = __float2bfloat16_rn(acc[mi][ni][i * 2 + 1] + bias[gn0 + 1]);
                }
            }
        }
    }
}

// ---------------------------------------------------------------------------
// Output projection + residual: y = ctx @ Wo^T + bo + x   (ctx bf16)
// ---------------------------------------------------------------------------
__global__ void __launch_bounds__(256)
gemm_oproj_kernel(const float* __restrict__ bo, const float* __restrict__ x)
{
    float acc[4][4][4];
    #pragma unroll
    for (int mi = 0; mi < 4; ++mi)
        #pragma unroll
        for (int ni = 0; ni < 4; ++ni) {
            acc[mi][ni][0] = 0.f; acc[mi][ni][1] = 0.f;
            acc[mi][ni][2] = 0.f; acc[mi][ni][3] = 0.f;
        }

    gemm_main_bf16(g_ctx, g_wob, acc);

    const int tid  = threadIdx.x;
    const int lane = tid & 31;
    const int warp = tid >> 5;
    const int wm   = (warp >> 2) * 64;
    const int wn   = (warp & 3) * 32;
    const int g    = lane >> 2;
    const int q    = lane & 3;
    const int m0   = blockIdx.y * 128;
    const int n0   = blockIdx.x * 128;

    #pragma unroll
    for (int mi = 0; mi < 4; ++mi) {
        #pragma unroll
        for (int i = 0; i < 2; ++i) {
            const int gm = m0 + wm + mi * 16 + g + i * 8;
            #pragma unroll
            for (int ni = 0; ni < 4; ++ni) {
                const int gn0 = n0 + wn + ni * 8 + q * 2;
                const size_t off = (size_t)gm * Dm + gn0;
                const float2 r = *(const float2*)&x[off];
                float2 v;
                v.x = acc[mi][ni][i * 2 + 0] + bo[gn0 + 0] + r.x;
                v.y = acc[mi][ni][i * 2 + 1] + bo[gn0 + 1] + r.y;
                *(float2*)&g_y[off] = v;
            }
        }
    }
}

// ---------------------------------------------------------------------------
// Causal flash attention, bf16 in/out. grid = (S/64, B*H), 128 thr = 4 warps.
// Q (pre-scaled), K bf16 [bh][s][d]; V bf16 [bh][d][s]; ctx bf16 out.
// smem: Ks[64][36] words (K; reused for P), Vt[64][36].
// ---------------------------------------------------------------------------
#define ALD 36

__global__ void __launch_bounds__(128)
attn_kernel(const __nv_bfloat16* __restrict__ Qg, const __nv_bfloat16* __restrict__ Kg,
            const __nv_bfloat16* __restrict__ Vg, __nv_bfloat16* __restrict__ ctx)
{
    __shared__ __align__(16) uint32_t Ks[64 * ALD];   // K tile, then P tile
    __shared__ __align__(16) uint32_t Vt[64 * ALD];   // [d][j/2]

    const int tid  = threadIdx.x;
    const int lane = tid & 31;
    const int warp = tid >> 5;
    const int g    = lane >> 2;   // 0..7
    const int q    = lane & 3;    // 0..3
    const int bh   = blockIdx.y;
    const int qb   = blockIdx.x;
    const int qi0  = qb * 64;
    const int wrow = warp * 16;

    const __nv_bfloat16* Qbh = Qg + (size_t)bh * Sm * DHm;
    const __nv_bfloat16* Kbh = Kg + (size_t)bh * Sm * DHm;
    const __nv_bfloat16* Vbh = Vg + (size_t)bh * DHm * Sm;

    // ldmatrix source addresses
    const int fr_row = (lane & 7) + ((lane & 16) >> 1);
    const int fr_wrd = (lane & 8) ? 4 : 0;
    const uint32_t ks_b = cvta_s(&Ks[fr_row * ALD + fr_wrd]);
    const uint32_t vt_b = cvta_s(&Vt[fr_row * ALD + fr_wrd]);
    const uint32_t p_a  = cvta_s(&Ks[(wrow + (lane & 15)) * ALD + (lane >> 4) * 4]);

    // Q fragments: direct bf16-pair loads (already scaled by 1/8)
    uint32_t qa[4][4];
    {
        const size_t r0 = (size_t)(qi0 + wrow + g) * DHm;
        const size_t r1 = r0 + 8 * DHm;
        #pragma unroll
        for (int kf = 0; kf < 4; ++kf) {
            const int d0 = kf * 16 + 2 * q;
            qa[kf][0] = *(const uint32_t*)&Qbh[r0 + d0];
            qa[kf][1] = *(const uint32_t*)&Qbh[r1 + d0];
            qa[kf][2] = *(const uint32_t*)&Qbh[r0 + d0 + 8];
            qa[kf][3] = *(const uint32_t*)&Qbh[r1 + d0 + 8];
        }
    }

    float m0 = -1e30f, m1 = -1e30f, l0 = 0.f, l1 = 0.f;
    float o[8][4];
    #pragma unroll
    for (int nf = 0; nf < 8; ++nf) {
        o[nf][0] = 0.f; o[nf][1] = 0.f; o[nf][2] = 0.f; o[nf][3] = 0.f;
    }

    for (int kt = 0; kt <= qb; ++kt) {
        const int kj0 = kt * 64;
        __syncthreads();   // previous iter's P/V reads complete

        // load K and V tiles: 16B bf16 copies, no conversion
        #pragma unroll
        for (int it = 0; it < 4; ++it) {
            const int idx = it * 128 + tid;          // 0..511
            const int row = idx >> 3;                // 0..63 (K: j ; V: d)
            const int cw  = idx & 7;                 // 16B chunk index
            *(uint4*)&Ks[row * ALD + cw * 4] =
                *(const uint4*)&Kbh[(size_t)(kj0 + row) * DHm + cw * 8];
            *(uint4*)&Vt[row * ALD + cw * 4] =
                *(const uint4*)&Vbh[(size_t)row * Sm + kj0 + cw * 8];
        }
        __syncthreads();

        // S = Q K^T  (per warp: 16 x 64; ldmatrix B)
        float sacc[8][4];
        #pragma unroll
        for (int nf = 0; nf < 8; ++nf) {
            sacc[nf][0] = 0.f; sacc[nf][1] = 0.f; sacc[nf][2] = 0.f; sacc[nf][3] = 0.f;
        }
        #pragma unroll
        for (int kf = 0; kf < 4; ++kf) {
            #pragma unroll
            for (int n2 = 0; n2 < 4; ++n2) {
                uint32_t b4[4];
                LDSM4(b4[0], b4[1], b4[2], b4[3],
                      ks_b + (n2 * 16 * ALD + kf * 8) * 4);
                mma_bf16(sacc[2 * n2],     qa[kf], b4);
                mma_bf16(sacc[2 * n2 + 1], qa[kf], b4 + 2);
            }
        }

        // causal mask on diagonal tile
        if (kt == qb) {
            const int r0l = wrow + g, r1l = r0l + 8;
            #pragma unroll
            for (int nf = 0; nf < 8; ++nf) {
                const int c = nf * 8 + 2 * q;
                if (c     > r0l) sacc[nf][0] = -1e30f;
                if (c + 1 > r0l) sacc[nf][1] = -1e30f;
                if (c     > r1l) sacc[nf][2] = -1e30f;
                if (c + 1 > r1l) sacc[nf][3] = -1e30f;
            }
        }

        // online softmax (rows live on 4 lanes: shfl over q)
        float mx0 = -1e30f, mx1 = -1e30f;
        #pragma unroll
        for (int nf = 0; nf < 8; ++nf) {
            mx0 = fmaxf(mx0, fmaxf(sacc[nf][0], sacc[nf][1]));
            mx1 = fmaxf(mx1, fmaxf(sacc[nf][2], sacc[nf][3]));
        }
        mx0 = fmaxf(mx0, __shfl_xor_sync(0xffffffffu, mx0, 1));
        mx0 = fmaxf(mx0, __shfl_xor_sync(0xffffffffu, mx0, 2));
        mx1 = fmaxf(mx1, __shfl_xor_sync(0xffffffffu, mx1, 1));
        mx1 = fmaxf(mx1, __shfl_xor_sync(0xffffffffu, mx1, 2));

        const float mn0 = fmaxf(m0, mx0);
        const float mn1 = fmaxf(m1, mx1);
        const float al0 = __expf(m0 - mn0);
        const float al1 = __expf(m1 - mn1);
        m0 = mn0; m1 = mn1;

        float rs0 = 0.f, rs1 = 0.f;
        #pragma unroll
        for (int nf = 0; nf < 8; ++nf) {
            sacc[nf][0] = __expf(sacc[nf][0] - mn0);
            sacc[nf][1] = __expf(sacc[nf][1] - mn0);
            sacc[nf][2] = __expf(sacc[nf][2] - mn1);
            sacc[nf][3] = __expf(sacc[nf][3] - mn1);
            rs0 += sacc[nf][0] + sacc[nf][1];
            rs1 += sacc[nf][2] + sacc[nf][3];
        }
        rs0 += __shfl_xor_sync(0xffffffffu, rs0, 1);
        rs0 += __shfl_xor_sync(0xffffffffu, rs0, 2);
        rs1 += __shfl_xor_sync(0xffffffffu, rs1, 1);
        rs1 += __shfl_xor_sync(0xffffffffu, rs1, 2);

        l0 = l0 * al0 + rs0;
        l1 = l1 * al1 + rs1;
        #pragma unroll
        for (int nf = 0; nf < 8; ++nf) {
            o[nf][0] *= al0; o[nf][1] *= al0;
            o[nf][2] *= al1; o[nf][3] *= al1;
        }

        __syncthreads();   // all warps done reading Ks -> reuse as P

        // store P (bf16 pairs of adjacent cols); rows are warp-private
        {
            const int r0l = wrow + g, r1l = r0l + 8;
            #pragma unroll
            for (int nf = 0; nf < 8; ++nf) {
                Ks[r0l * ALD + nf * 4 + q] = pack_bf16(sacc[nf][0], sacc[nf][1]);
                Ks[r1l * ALD + nf * 4 + q] = pack_bf16(sacc[nf][2], sacc[nf][3]);
            }
        }
        __syncwarp();

        // O += P @ V  (ldmatrix A from P rows + B from Vt)
        #pragma unroll
        for (int kf = 0; kf < 4; ++kf) {
            uint32_t a4[4];
            LDSM4(a4[0], a4[1], a4[2], a4[3], p_a + (kf * 8) * 4);
            #pragma unroll
            for (int n2 = 0; n2 < 4; ++n2) {
                uint32_t b4[4];
                LDSM4(b4[0], b4[1], b4[2], b4[3],
                      vt_b + (n2 * 16 * ALD + kf * 8) * 4);
                mma_bf16(o[2 * n2],     a4, b4);
                mma_bf16(o[2 * n2 + 1], a4, b4 + 2);
            }
        }
    }

    // epilogue: divide by l, write ctx bf16 [b][s][h*64+d]
    const int b = bh >> 4, h = bh & 15;
    const float inv0 = 1.0f / l0;
    const float inv1 = 1.0f / l1;
    const int s0 = qi0 + wrow + g;
    #pragma unroll
    for (int nf = 0; nf < 8; ++nf) {
        const int dd = h * DHm + nf * 8 + 2 * q;
        *(uint32_t*)&ctx[((size_t)(b * Sm + s0)) * Dm + dd] =
            pack_bf16(o[nf][0] * inv0, o[nf][1] * inv0);
        *(uint32_t*)&ctx[((size_t)(b * Sm + s0 + 8)) * Dm + dd] =
            pack_bf16(o[nf][2] * inv1, o[nf][3] * inv1);
    }
}

// ---------------------------------------------------------------------------
// LayerNorm over last dim (1024). One block per row, 256 threads x 4 floats.
// ---------------------------------------------------------------------------
__global__ void __launch_bounds__(256)
ln_kernel(const float* __restrict__ y, const float* __restrict__ gam,
          const float* __restrict__ bet, float* __restrict__ out)
{
    __shared__ float red[2][8];
    const int row = blockIdx.x;
    const int tid = threadIdx.x;

    const float4 v = *(const float4*)&y[(size_t)row * Dm + tid * 4];
    float s  = v.x + v.y + v.z + v.w;
    float ss = v.x * v.x + v.y * v.y + v.z * v.z + v.w * v.w;

    #pragma unroll
    for (int off = 16; off > 0; off >>= 1) {
        s  += __shfl_xor_sync(0xffffffffu, s, off);
        ss += __shfl_xor_sync(0xffffffffu, ss, off);
    }
    const int wid = tid >> 5, lane = tid & 31;
    if (lane == 0) { red[0][wid] = s; red[1][wid] = ss; }
    __syncthreads();
    if (tid == 0) {
        float S = 0.f, SS = 0.f;
        #pragma unroll
        for (int w = 0; w < 8; ++w) { S += red[0][w]; SS += red[1][w]; }
        red[0][0] = S; red[1][0] = SS;
    }
    __syncthreads();

    const float mu   = red[0][0] * (1.0f / Dm);
    const float var  = red[1][0] * (1.0f / Dm) - mu * mu;
    const float rstd = rsqrtf(var + 1e-5f);

    const float4 g4 = *(const float4*)&gam[tid * 4];
    const float4 b4 = *(const float4*)&bet[tid * 4];
    float4 r;
    r.x = (v.x - mu) * rstd * g4.x + b4.x;
    r.y = (v.y - mu) * rstd * g4.y + b4.y;
    r.z = (v.z - mu) * rstd * g4.z + b4.z;
    r.w = (v.w - mu) * rstd * g4.w + b4.w;
    *(float4*)&out[(size_t)row * Dm + tid * 4] = r;
}

// ---------------------------------------------------------------------------
extern "C" void kernel_launch(void* const* d_in, const int* in_sizes, int n_in,
                              void* d_out, int out_size)
{
    const float* x    = (const float*)d_in[0];
    const float* Wq   = (const float*)d_in[1];
    const float* bq   = (const float*)d_in[2];
    const float* Wk   = (const float*)d_in[3];
    const float* bk   = (const float*)d_in[4];
    const float* Wv   = (const float*)d_in[5];
    const float* bv   = (const float*)d_in[6];
    const float* Wo   = (const float*)d_in[7];
    const float* bo   = (const float*)d_in[8];
    const float* ln_g = (const float*)d_in[9];
    const float* ln_b = (const float*)d_in[10];
    float* out = (float*)d_out;

    __nv_bfloat16 *xb_p, *wq_p, *wk_p, *wv_p, *wo_p, *q_p, *k_p, *v_p, *ctx_p;
    float* y_p;
    cudaGetSymbolAddress((void**)&xb_p,  g_xb);
    cudaGetSymbolAddress((void**)&wq_p,  g_wqb);
    cudaGetSymbolAddress((void**)&wk_p,  g_wkb);
    cudaGetSymbolAddress((void**)&wv_p,  g_wvb);
    cudaGetSymbolAddress((void**)&wo_p,  g_wob);
    cudaGetSymbolAddress((void**)&q_p,   g_q);
    cudaGetSymbolAddress((void**)&k_p,   g_k);
    cudaGetSymbolAddress((void**)&v_p,   g_v);
    cudaGetSymbolAddress((void**)&ctx_p, g_ctx);
    cudaGetSymbolAddress((void**)&y_p,   g_y);

    const int nx4 = Bm * Sm * Dm / 4;   // 1M
    const int nw4 = Dm * Dm / 4;        // 256K
    to_bf16_kernel<<<(nx4 + 255) / 256, 256>>>(x,  xb_p, nx4);
    to_bf16_kernel<<<(nw4 + 255) / 256, 256>>>(Wq, wq_p, nw4);
    to_bf16_kernel<<<(nw4 + 255) / 256, 256>>>(Wk, wk_p, nw4);
    to_bf16_kernel<<<(nw4 + 255) / 256, 256>>>(Wv, wv_p, nw4);
    to_bf16_kernel<<<(nw4 + 255) / 256, 256>>>(Wo, wo_p, nw4);

    gemm_qkv_kernel<<<dim3(8, 32, 3), 256>>>(bq, bk, bv);
    attn_kernel<<<dim3(32, 32), 128>>>(q_p, k_p, v_p, ctx_p);
    gemm_oproj_kernel<<<dim3(8, 32), 256>>>(bo, x);
    ln_kernel<<<4096, 256>>>(y_p, ln_g, ln_b, out);
}

// round 12
// speedup vs baseline: 4.6795x; 1.1557x over previous
#include <cuda_runtime.h>
#include <cuda_bf16.h>
#include <math.h>
#include <float.h>
#include <stdint.h>

#define Dm 1024
#define Sm 2048
#define Bm 2
#define Hm 16
#define DHm 64
#define BHm (Bm * Hm)

// Scratch (static device arrays; no allocations in kernel_launch)
__device__ __nv_bfloat16 g_xb[Bm * Sm * Dm];      // x in bf16
__device__ __nv_bfloat16 g_wqb[Dm * Dm];
__device__ __nv_bfloat16 g_wkb[Dm * Dm];
__device__ __nv_bfloat16 g_wvb[Dm * Dm];
__device__ __nv_bfloat16 g_wob[Dm * Dm];
__device__ __nv_bfloat16 g_q[BHm * Sm * DHm];     // [bh][s][d], pre-scaled by 1/8
__device__ __nv_bfloat16 g_k[BHm * Sm * DHm];     // [bh][s][d]
__device__ __nv_bfloat16 g_v[BHm * DHm * Sm];     // [bh][d][s]
__device__ __nv_bfloat16 g_ctx[Bm * Sm * Dm];     // [b][s][h*64+d]
__device__ float g_y[Bm * Sm * Dm];               // pre-LN residual sum (fp32)

// ---------------------------------------------------------------------------
// helpers
// ---------------------------------------------------------------------------
__device__ __forceinline__ uint32_t pack_bf16(float lo, float hi) {
    uint32_t r;
    asm("cvt.rn.bf16x2.f32 %0, %1, %2;" : "=r"(r) : "f"(hi), "f"(lo));
    return r;
}

__device__ __forceinline__ void mma_bf16(float c[4], const uint32_t a[4], const uint32_t b[2]) {
    asm volatile(
        "mma.sync.aligned.m16n8k16.row.col.f32.bf16.bf16.f32 "
        "{%0,%1,%2,%3}, {%4,%5,%6,%7}, {%8,%9}, {%0,%1,%2,%3};"
        : "+f"(c[0]), "+f"(c[1]), "+f"(c[2]), "+f"(c[3])
        : "r"(a[0]), "r"(a[1]), "r"(a[2]), "r"(a[3]), "r"(b[0]), "r"(b[1]));
}

__device__ __forceinline__ uint32_t cvta_s(const void* p) {
    return (uint32_t)__cvta_generic_to_shared(p);
}

#define LDSM4(R0, R1, R2, R3, ADDR) \
    asm volatile("ldmatrix.sync.aligned.m8n8.x4.shared.b16 {%0,%1,%2,%3}, [%4];" \
        : "=r"(R0), "=r"(R1), "=r"(R2), "=r"(R3) : "r"(ADDR))

#define CP16(DST, SRC) \
    asm volatile("cp.async.cg.shared.global [%0], [%1], 16;" :: "r"(DST), "l"(SRC))
#define CP_COMMIT() asm volatile("cp.async.commit_group;")
#define CP_WAIT0()  asm volatile("cp.async.wait_group 0;")

// ---------------------------------------------------------------------------
// fp32 -> bf16 bulk convert
// ---------------------------------------------------------------------------
__global__ void __launch_bounds__(256)
to_bf16_kernel(const float* __restrict__ src, __nv_bfloat16* __restrict__ dst, int n4)
{
    const int i = blockIdx.x * blockDim.x + threadIdx.x;
    if (i < n4) {
        const float4 v = ((const float4*)src)[i];
        uint2 w;
        w.x = pack_bf16(v.x, v.y);
        w.y = pack_bf16(v.z, v.w);
        ((uint2*)dst)[i] = w;
    }
}

#define SSTR 20   // GEMM smem row stride in words (BK=32: 16 data words + 4 pad)

// ---------------------------------------------------------------------------
// bf16 GEMM mainloop: C[128x128] of A[M,K] @ W[N,K]^T, K=1024, BK=32.
// 256 threads = 8 warps, warp tile 64x32. 2-stage cp.async, ldmatrix,
// 1 sync per BK=32 tile (32 iterations).
// ---------------------------------------------------------------------------
__device__ __forceinline__ void gemm_main_bf16(const __nv_bfloat16* __restrict__ A,
                                               const __nv_bfloat16* __restrict__ Wt,
                                               float acc[4][4][4])
{
    __shared__ __align__(16) uint32_t As[2][128 * SSTR];
    __shared__ __align__(16) uint32_t Bs[2][128 * SSTR];

    const int tid  = threadIdx.x;
    const int lane = tid & 31;
    const int warp = tid >> 5;
    const int wm   = (warp >> 2) * 64;
    const int wn   = (warp & 3) * 32;
    const int m0   = blockIdx.y * 128;
    const int n0   = blockIdx.x * 128;

    // fill indexing: 2 A-chunks + 2 B-chunks per thread per stage
    const int fr0 = tid >> 2;               // rows 0..63   (it=0)
    const int fr1 = (256 + tid) >> 2;       // rows 64..127 (it=1)
    const int fc  = tid & 3;                // 16B chunk 0..3

    // ldmatrix per-thread source addresses
    const int a_row  = wm + (lane & 15);
    const int a_word = (lane >> 4) * 4;
    const int b_row  = wn + (lane & 7) + ((lane & 16) >> 1);
    const int b_word = (lane & 8) ? 4 : 0;
    uint32_t aaddr[2], baddr[2], sA[2][2], sB[2][2];
    #pragma unroll
    for (int s = 0; s < 2; ++s) {
        aaddr[s] = cvta_s(&As[s][a_row * SSTR + a_word]);
        baddr[s] = cvta_s(&Bs[s][b_row * SSTR + b_word]);
        sA[s][0] = cvta_s(&As[s][fr0 * SSTR + fc * 4]);
        sA[s][1] = cvta_s(&As[s][fr1 * SSTR + fc * 4]);
        sB[s][0] = cvta_s(&Bs[s][fr0 * SSTR + fc * 4]);
        sB[s][1] = cvta_s(&Bs[s][fr1 * SSTR + fc * 4]);
    }

    const __nv_bfloat16* Ap0 = A  + (size_t)(m0 + fr0) * Dm + fc * 8;
    const __nv_bfloat16* Ap1 = A  + (size_t)(m0 + fr1) * Dm + fc * 8;
    const __nv_bfloat16* Bp0 = Wt + (size_t)(n0 + fr0) * Dm + fc * 8;
    const __nv_bfloat16* Bp1 = Wt + (size_t)(n0 + fr1) * Dm + fc * 8;

    // prologue: stage 0 (k 0..31)
    CP16(sA[0][0], Ap0); CP16(sA[0][1], Ap1);
    CP16(sB[0][0], Bp0); CP16(sB[0][1], Bp1);
    CP_COMMIT();
    CP_WAIT0();
    __syncthreads();

    for (int kt = 0; kt < 32; ++kt) {
        const int cur = kt & 1;
        if (kt < 31) {
            const int nxt = cur ^ 1;
            const int kb = (kt + 1) * 32;
            CP16(sA[nxt][0], Ap0 + kb); CP16(sA[nxt][1], Ap1 + kb);
            CP16(sB[nxt][0], Bp0 + kb); CP16(sB[nxt][1], Bp1 + kb);
            CP_COMMIT();
        }

        #pragma unroll
        for (int slab = 0; slab < 2; ++slab) {
            const uint32_t soff = slab * 8 * 4;   // +8 words
            uint32_t a[4][4], b[4][2];
            #pragma unroll
            for (int mi = 0; mi < 4; ++mi)
                LDSM4(a[mi][0], a[mi][1], a[mi][2], a[mi][3],
                      aaddr[cur] + (mi * 16 * SSTR) * 4 + soff);
            #pragma unroll
            for (int n2 = 0; n2 < 2; ++n2)
                LDSM4(b[2 * n2][0], b[2 * n2][1], b[2 * n2 + 1][0], b[2 * n2 + 1][1],
                      baddr[cur] + (n2 * 16 * SSTR) * 4 + soff);
            #pragma unroll
            for (int mi = 0; mi < 4; ++mi)
                #pragma unroll
                for (int ni = 0; ni < 4; ++ni)
                    mma_bf16(acc[mi][ni], a[mi], b[ni]);
        }

        if (kt < 31) {
            CP_WAIT0();
            __syncthreads();
        }
    }
}

// ---------------------------------------------------------------------------
// QKV projection. grid = (8, 32, 3): z selects Q/K/V.
// Q (scaled 1/8), K stored bf16 [bh][s][d]; V stored bf16 [bh][d][s].
// ---------------------------------------------------------------------------
__global__ void __launch_bounds__(256)
gemm_qkv_kernel(const float* __restrict__ bq, const float* __restrict__ bk,
                const float* __restrict__ bv)
{
    const int z = blockIdx.z;
    const __nv_bfloat16* W = (z == 0) ? g_wqb : (z == 1) ? g_wkb : g_wvb;
    const float* bias      = (z == 0) ? bq : (z == 1) ? bk : bv;

    float acc[4][4][4];
    #pragma unroll
    for (int mi = 0; mi < 4; ++mi)
        #pragma unroll
        for (int ni = 0; ni < 4; ++ni) {
            acc[mi][ni][0] = 0.f; acc[mi][ni][1] = 0.f;
            acc[mi][ni][2] = 0.f; acc[mi][ni][3] = 0.f;
        }

    gemm_main_bf16(g_xb, W, acc);

    const int tid  = threadIdx.x;
    const int lane = tid & 31;
    const int warp = tid >> 5;
    const int wm   = (warp >> 2) * 64;
    const int wn   = (warp & 3) * 32;
    const int g    = lane >> 2;
    const int q    = lane & 3;
    const int m0   = blockIdx.y * 128;
    const int n0   = blockIdx.x * 128;

    if (z < 2) {
        __nv_bfloat16* dst = (z == 0) ? g_q : g_k;
        const float sc = (z == 0) ? 0.125f : 1.0f;
        #pragma unroll
        for (int mi = 0; mi < 4; ++mi) {
            #pragma unroll
            for (int i = 0; i < 2; ++i) {
                const int gm = m0 + wm + mi * 16 + g + i * 8;
                const int b  = gm >> 11;
                const int s  = gm & 2047;
                #pragma unroll
                for (int ni = 0; ni < 4; ++ni) {
                    const int gn0 = n0 + wn + ni * 8 + q * 2;
                    const int h   = gn0 >> 6, dd0 = gn0 & 63;
                    const uint32_t w = pack_bf16((acc[mi][ni][i * 2 + 0] + bias[gn0 + 0]) * sc,
                                                 (acc[mi][ni][i * 2 + 1] + bias[gn0 + 1]) * sc);
                    *(uint32_t*)&dst[(((size_t)(b * Hm + h) * Sm + s) * DHm) + dd0] = w;
                }
            }
        }
    } else {
        // V: [bh][d][s] scatter (2B stores)
        #pragma unroll
        for (int mi = 0; mi < 4; ++mi) {
            #pragma unroll
            for (int i = 0; i < 2; ++i) {
                const int gm = m0 + wm + mi * 16 + g + i * 8;
                const int b  = gm >> 11;
                const int s  = gm & 2047;
                #pragma unroll
                for (int ni = 0; ni < 4; ++ni) {
                    const int gn0 = n0 + wn + ni * 8 + q * 2;
                    const int h   = gn0 >> 6, dd0 = gn0 & 63;
                    const size_t base = ((size_t)(b * Hm + h) * DHm + dd0) * Sm + s;
                    g_v[base]      = __float2bfloat16_rn(acc[mi][ni][i * 2 + 0] + bias[gn0 + 0]);
                    g_v[base + Sm] = __float2bfloat16_rn(acc[mi][ni][i * 2 + 1] + bias[gn0 + 1]);
                }
            }
        }
    }
}

// ---------------------------------------------------------------------------
// Output projection + residual: y = ctx @ Wo^T + bo + x   (ctx bf16)
// ---------------------------------------------------------------------------
__global__ void __launch_bounds__(256)
gemm_oproj_kernel(const float* __restrict__ bo, const float* __restrict__ x)
{
    float acc[4][4][4];
    #pragma unroll
    for (int mi = 0; mi < 4; ++mi)
        #pragma unroll
        for (int ni = 0; ni < 4; ++ni) {
            acc[mi][ni][0] = 0.f; acc[mi][ni][1] = 0.f;
            acc[mi][ni][2] = 0.f; acc[mi][ni][3] = 0.f;
        }

    gemm_main_bf16(g_ctx, g_wob, acc);

    const int tid  = threadIdx.x;
    const int lane = tid & 31;
    const int warp = tid >> 5;
    const int wm   = (warp >> 2) * 64;
    const int wn   = (warp & 3) * 32;
    const int g    = lane >> 2;
    const int q    = lane & 3;
    const int m0   = blockIdx.y * 128;
    const int n0   = blockIdx.x * 128;

    #pragma unroll
    for (int mi = 0; mi < 4; ++mi) {
        #pragma unroll
        for (int i = 0; i < 2; ++i) {
            const int gm = m0 + wm + mi * 16 + g + i * 8;
            #pragma unroll
            for (int ni = 0; ni < 4; ++ni) {
                const int gn0 = n0 + wn + ni * 8 + q * 2;
                const size_t off = (size_t)gm * Dm + gn0;
                const float2 r = *(const float2*)&x[off];
                float2 v;
                v.x = acc[mi][ni][i * 2 + 0] + bo[gn0 + 0] + r.x;
                v.y = acc[mi][ni][i * 2 + 1] + bo[gn0 + 1] + r.y;
                *(float2*)&g_y[off] = v;
            }
        }
    }
}

// ---------------------------------------------------------------------------
// Causal flash attention, bf16, 128-row q-tiles. grid = (16, 32), 256 thr.
// Q (pre-scaled), K bf16 [bh][s][d]; V bf16 [bh][d][s]; ctx bf16 out.
// smem: Ks[64][36] (K), Vt[64][36] (V), Ps[128][36] (P). 36KB.
// Heavy blocks first: qb = 15 - blockIdx.x.
// ---------------------------------------------------------------------------
#define ALD 36

__global__ void __launch_bounds__(256)
attn_kernel(const __nv_bfloat16* __restrict__ Qg, const __nv_bfloat16* __restrict__ Kg,
            const __nv_bfloat16* __restrict__ Vg, __nv_bfloat16* __restrict__ ctx)
{
    __shared__ __align__(16) uint32_t Ks[64 * ALD];
    __shared__ __align__(16) uint32_t Vt[64 * ALD];
    __shared__ __align__(16) uint32_t Ps[128 * ALD];

    const int tid  = threadIdx.x;
    const int lane = tid & 31;
    const int warp = tid >> 5;          // 0..7
    const int g    = lane >> 2;
    const int q    = lane & 3;
    const int bh   = blockIdx.y;
    const int qb   = (int)(gridDim.x - 1) - (int)blockIdx.x;   // heavy first
    const int qi0  = qb * 128;
    const int wrow = warp * 16;         // 0..112

    const __nv_bfloat16* Qbh = Qg + (size_t)bh * Sm * DHm;
    const __nv_bfloat16* Kbh = Kg + (size_t)bh * Sm * DHm;
    const __nv_bfloat16* Vbh = Vg + (size_t)bh * DHm * Sm;

    // ldmatrix source addresses
    const int fr_row = (lane & 7) + ((lane & 16) >> 1);
    const int fr_wrd = (lane & 8) ? 4 : 0;
    const uint32_t ks_b = cvta_s(&Ks[fr_row * ALD + fr_wrd]);
    const uint32_t vt_b = cvta_s(&Vt[fr_row * ALD + fr_wrd]);
    const uint32_t p_a  = cvta_s(&Ps[(wrow + (lane & 15)) * ALD + (lane >> 4) * 4]);

    // Q fragments (already scaled by 1/8)
    uint32_t qa[4][4];
    {
        const size_t r0 = (size_t)(qi0 + wrow + g) * DHm;
        const size_t r1 = r0 + 8 * DHm;
        #pragma unroll
        for (int kf = 0; kf < 4; ++kf) {
            const int d0 = kf * 16 + 2 * q;
            qa[kf][0] = *(const uint32_t*)&Qbh[r0 + d0];
            qa[kf][1] = *(const uint32_t*)&Qbh[r1 + d0];
            qa[kf][2] = *(const uint32_t*)&Qbh[r0 + d0 + 8];
            qa[kf][3] = *(const uint32_t*)&Qbh[r1 + d0 + 8];
        }
    }

    float m0 = -1e30f, m1 = -1e30f, l0 = 0.f, l1 = 0.f;
    float o[8][4];
    #pragma unroll
    for (int nf = 0; nf < 8; ++nf) {
        o[nf][0] = 0.f; o[nf][1] = 0.f; o[nf][2] = 0.f; o[nf][3] = 0.f;
    }

    const int ntiles = 2 * qb + 2;
    for (int kt = 0; kt < ntiles; ++kt) {
        const int kj0 = kt * 64;
        __syncthreads();   // prior S-mma (Ks) and PV-mma (Vt) reads complete

        // load K [j][d] and V [d][j] tiles: 16B bf16 copies
        #pragma unroll
        for (int it = 0; it < 2; ++it) {
            const int idx = it * 256 + tid;          // 0..511
            const int row = idx >> 3;                // 0..63
            const int cw  = idx & 7;
            *(uint4*)&Ks[row * ALD + cw * 4] =
                *(const uint4*)&Kbh[(size_t)(kj0 + row) * DHm + cw * 8];
            *(uint4*)&Vt[row * ALD + cw * 4] =
                *(const uint4*)&Vbh[(size_t)row * Sm + kj0 + cw * 8];
        }
        __syncthreads();

        // S = Q K^T  (per warp: 16 x 64)
        float sacc[8][4];
        #pragma unroll
        for (int nf = 0; nf < 8; ++nf) {
            sacc[nf][0] = 0.f; sacc[nf][1] = 0.f; sacc[nf][2] = 0.f; sacc[nf][3] = 0.f;
        }
        #pragma unroll
        for (int kf = 0; kf < 4; ++kf) {
            #pragma unroll
            for (int n2 = 0; n2 < 4; ++n2) {
                uint32_t b4[4];
                LDSM4(b4[0], b4[1], b4[2], b4[3],
                      ks_b + (n2 * 16 * ALD + kf * 8) * 4);
                mma_bf16(sacc[2 * n2],     qa[kf], b4);
                mma_bf16(sacc[2 * n2 + 1], qa[kf], b4 + 2);
            }
        }

        // causal mask (only last two tiles can be partial)
        if (kt >= 2 * qb) {
            const int rg0 = qi0 + wrow + g, rg1 = rg0 + 8;
            #pragma unroll
            for (int nf = 0; nf < 8; ++nf) {
                const int cg = kj0 + nf * 8 + 2 * q;
                if (cg     > rg0) sacc[nf][0] = -1e30f;
                if (cg + 1 > rg0) sacc[nf][1] = -1e30f;
                if (cg     > rg1) sacc[nf][2] = -1e30f;
                if (cg + 1 > rg1) sacc[nf][3] = -1e30f;
            }
        }

        // online softmax
        float mx0 = -1e30f, mx1 = -1e30f;
        #pragma unroll
        for (int nf = 0; nf < 8; ++nf) {
            mx0 = fmaxf(mx0, fmaxf(sacc[nf][0], sacc[nf][1]));
            mx1 = fmaxf(mx1, fmaxf(sacc[nf][2], sacc[nf][3]));
        }
        mx0 = fmaxf(mx0, __shfl_xor_sync(0xffffffffu, mx0, 1));
        mx0 = fmaxf(mx0, __shfl_xor_sync(0xffffffffu, mx0, 2));
        mx1 = fmaxf(mx1, __shfl_xor_sync(0xffffffffu, mx1, 1));
        mx1 = fmaxf(mx1, __shfl_xor_sync(0xffffffffu, mx1, 2));

        const float mn0 = fmaxf(m0, mx0);
        const float mn1 = fmaxf(m1, mx1);
        const float al0 = __expf(m0 - mn0);
        const float al1 = __expf(m1 - mn1);
        m0 = mn0; m1 = mn1;

        float rs0 = 0.f, rs1 = 0.f;
        #pragma unroll
        for (int nf = 0; nf < 8; ++nf) {
            sacc[nf][0] = __expf(sacc[nf][0] - mn0);
            sacc[nf][1] = __expf(sacc[nf][1] - mn0);
            sacc[nf][2] = __expf(sacc[nf][2] - mn1);
            sacc[nf][3] = __expf(sacc[nf][3] - mn1);
            rs0 += sacc[nf][0] + sacc[nf][1];
            rs1 += sacc[nf][2] + sacc[nf][3];
        }
        rs0 += __shfl_xor_sync(0xffffffffu, rs0, 1);
        rs0 += __shfl_xor_sync(0xffffffffu, rs0, 2);
        rs1 += __shfl_xor_sync(0xffffffffu, rs1, 1);
        rs1 += __shfl_xor_sync(0xffffffffu, rs1, 2);

        l0 = l0 * al0 + rs0;
        l1 = l1 * al1 + rs1;
        #pragma unroll
        for (int nf = 0; nf < 8; ++nf) {
            o[nf][0] *= al0; o[nf][1] *= al0;
            o[nf][2] *= al1; o[nf][3] *= al1;
        }

        // store P into warp-private rows of Ps (no cross-warp sync needed)
        {
            const int r0l = wrow + g, r1l = r0l + 8;
            #pragma unroll
            for (int nf = 0; nf < 8; ++nf) {
                Ps[r0l * ALD + nf * 4 + q] = pack_bf16(sacc[nf][0], sacc[nf][1]);
                Ps[r1l * ALD + nf * 4 + q] = pack_bf16(sacc[nf][2], sacc[nf][3]);
            }
        }
        __syncwarp();

        // O += P @ V
        #pragma unroll
        for (int kf = 0; kf < 4; ++kf) {
            uint32_t a4[4];
            LDSM4(a4[0], a4[1], a4[2], a4[3], p_a + (kf * 8) * 4);
            #pragma unroll
            for (int n2 = 0; n2 < 4; ++n2) {
                uint32_t b4[4];
                LDSM4(b4[0], b4[1], b4[2], b4[3],
                      vt_b + (n2 * 16 * ALD + kf * 8) * 4);
                mma_bf16(o[2 * n2],     a4, b4);
                mma_bf16(o[2 * n2 + 1], a4, b4 + 2);
            }
        }
    }

    // epilogue: divide by l, write ctx bf16 [b][s][h*64+d]
    const int b = bh >> 4, h = bh & 15;
    const float inv0 = 1.0f / l0;
    const float inv1 = 1.0f / l1;
    const int s0 = qi0 + wrow + g;
    #pragma unroll
    for (int nf = 0; nf < 8; ++nf) {
        const int dd = h * DHm + nf * 8 + 2 * q;
        *(uint32_t*)&ctx[((size_t)(b * Sm + s0)) * Dm + dd] =
            pack_bf16(o[nf][0] * inv0, o[nf][1] * inv0);
        *(uint32_t*)&ctx[((size_t)(b * Sm + s0 + 8)) * Dm + dd] =
            pack_bf16(o[nf][2] * inv1, o[nf][3] * inv1);
    }
}

// ---------------------------------------------------------------------------
// LayerNorm over last dim (1024). One block per row, 256 threads x 4 floats.
// ---------------------------------------------------------------------------
__global__ void __launch_bounds__(256)
ln_kernel(const float* __restrict__ y, const float* __restrict__ gam,
          const float* __restrict__ bet, float* __restrict__ out)
{
    __shared__ float red[2][8];
    const int row = blockIdx.x;
    const int tid = threadIdx.x;

    const float4 v = *(const float4*)&y[(size_t)row * Dm + tid * 4];
    float s  = v.x + v.y + v.z + v.w;
    float ss = v.x * v.x + v.y * v.y + v.z * v.z + v.w * v.w;

    #pragma unroll
    for (int off = 16; off > 0; off >>= 1) {
        s  += __shfl_xor_sync(0xffffffffu, s, off);
        ss += __shfl_xor_sync(0xffffffffu, ss, off);
    }
    const int wid = tid >> 5, lane = tid & 31;
    if (lane == 0) { red[0][wid] = s; red[1][wid] = ss; }
    __syncthreads();
    if (tid == 0) {
        float S = 0.f, SS = 0.f;
        #pragma unroll
        for (int w = 0; w < 8; ++w) { S += red[0][w]; SS += red[1][w]; }
        red[0][0] = S; red[1][0] = SS;
    }
    __syncthreads();

    const float mu   = red[0][0] * (1.0f / Dm);
    const float var  = red[1][0] * (1.0f / Dm) - mu * mu;
    const float rstd = rsqrtf(var + 1e-5f);

    const float4 g4 = *(const float4*)&gam[tid * 4];
    const float4 b4 = *(const float4*)&bet[tid * 4];
    float4 r;
    r.x = (v.x - mu) * rstd * g4.x + b4.x;
    r.y = (v.y - mu) * rstd * g4.y + b4.y;
    r.z = (v.z - mu) * rstd * g4.z + b4.z;
    r.w = (v.w - mu) * rstd * g4.w + b4.w;
    *(float4*)&out[(size_t)row * Dm + tid * 4] = r;
}

// ---------------------------------------------------------------------------
extern "C" void kernel_launch(void* const* d_in, const int* in_sizes, int n_in,
                              void* d_out, int out_size)
{
    const float* x    = (const float*)d_in[0];
    const float* Wq   = (const float*)d_in[1];
    const float* bq   = (const float*)d_in[2];
    const float* Wk   = (const float*)d_in[3];
    const float* bk   = (const float*)d_in[4];
    const float* Wv   = (const float*)d_in[5];
    const float* bv   = (const float*)d_in[6];
    const float* Wo   = (const float*)d_in[7];
    const float* bo   = (const float*)d_in[8];
    const float* ln_g = (const float*)d_in[9];
    const float* ln_b = (const float*)d_in[10];
    float* out = (float*)d_out;

    __nv_bfloat16 *xb_p, *wq_p, *wk_p, *wv_p, *wo_p, *q_p, *k_p, *v_p, *ctx_p;
    float* y_p;
    cudaGetSymbolAddress((void**)&xb_p,  g_xb);
    cudaGetSymbolAddress((void**)&wq_p,  g_wqb);
    cudaGetSymbolAddress((void**)&wk_p,  g_wkb);
    cudaGetSymbolAddress((void**)&wv_p,  g_wvb);
    cudaGetSymbolAddress((void**)&wo_p,  g_wob);
    cudaGetSymbolAddress((void**)&q_p,   g_q);
    cudaGetSymbolAddress((void**)&k_p,   g_k);
    cudaGetSymbolAddress((void**)&v_p,   g_v);
    cudaGetSymbolAddress((void**)&ctx_p, g_ctx);
    cudaGetSymbolAddress((void**)&y_p,   g_y);

    const int nx4 = Bm * Sm * Dm / 4;
    const int nw4 = Dm * Dm / 4;
    to_bf16_kernel<<<(nx4 + 255) / 256, 256>>>(x,  xb_p, nx4);
    to_bf16_kernel<<<(nw4 + 255) / 256, 256>>>(Wq, wq_p, nw4);
    to_bf16_kernel<<<(nw4 + 255) / 256, 256>>>(Wk, wk_p, nw4);
    to_bf16_kernel<<<(nw4 + 255) / 256, 256>>>(Wv, wv_p, nw4);
    to_bf16_kernel<<<(nw4 + 255) / 256, 256>>>(Wo, wo_p, nw4);

    gemm_qkv_kernel<<<dim3(8, 32, 3), 256>>>(bq, bk, bv);
    attn_kernel<<<dim3(16, 32), 256>>>(q_p, k_p, v_p, ctx_p);
    gemm_oproj_kernel<<<dim3(8, 32), 256>>>(bo, x);
    ln_kernel<<<4096, 256>>>(y_p, ln_g, ln_b, out);
}

// round 13
// speedup vs baseline: 5.0044x; 1.0694x over previous
#include <cuda_runtime.h>
#include <cuda_bf16.h>
#include <math.h>
#include <float.h>
#include <stdint.h>

#define Dm 1024
#define Sm 2048
#define Bm 2
#define Hm 16
#define DHm 64
#define BHm (Bm * Hm)

// Scratch (static device arrays; no allocations in kernel_launch)
__device__ __nv_bfloat16 g_xb[Bm * Sm * Dm];      // x in bf16
__device__ __nv_bfloat16 g_wqb[Dm * Dm];
__device__ __nv_bfloat16 g_wkb[Dm * Dm];
__device__ __nv_bfloat16 g_wvb[Dm * Dm];
__device__ __nv_bfloat16 g_wob[Dm * Dm];
__device__ __nv_bfloat16 g_q[BHm * Sm * DHm];     // [bh][s][d], pre-scaled by 1/8
__device__ __nv_bfloat16 g_k[BHm * Sm * DHm];     // [bh][s][d]
__device__ __nv_bfloat16 g_v[BHm * DHm * Sm];     // [bh][d][s]
__device__ __nv_bfloat16 g_ctx[Bm * Sm * Dm];     // [b][s][h*64+d]
__device__ float g_y[Bm * Sm * Dm];               // pre-LN residual sum (fp32)

// ---------------------------------------------------------------------------
// helpers
// ---------------------------------------------------------------------------
__device__ __forceinline__ uint32_t pack_bf16(float lo, float hi) {
    uint32_t r;
    asm("cvt.rn.bf16x2.f32 %0, %1, %2;" : "=r"(r) : "f"(hi), "f"(lo));
    return r;
}

__device__ __forceinline__ void mma_bf16(float c[4], const uint32_t a[4], const uint32_t b[2]) {
    asm volatile(
        "mma.sync.aligned.m16n8k16.row.col.f32.bf16.bf16.f32 "
        "{%0,%1,%2,%3}, {%4,%5,%6,%7}, {%8,%9}, {%0,%1,%2,%3};"
        : "+f"(c[0]), "+f"(c[1]), "+f"(c[2]), "+f"(c[3])
        : "r"(a[0]), "r"(a[1]), "r"(a[2]), "r"(a[3]), "r"(b[0]), "r"(b[1]));
}

__device__ __forceinline__ uint32_t cvta_s(const void* p) {
    return (uint32_t)__cvta_generic_to_shared(p);
}

#define LDSM4(R0, R1, R2, R3, ADDR) \
    asm volatile("ldmatrix.sync.aligned.m8n8.x4.shared.b16 {%0,%1,%2,%3}, [%4];" \
        : "=r"(R0), "=r"(R1), "=r"(R2), "=r"(R3) : "r"(ADDR))

#define CP16(DST, SRC) \
    asm volatile("cp.async.cg.shared.global [%0], [%1], 16;" :: "r"(DST), "l"(SRC))
#define CP_COMMIT() asm volatile("cp.async.commit_group;")
#define CP_WAIT0()  asm volatile("cp.async.wait_group 0;")
#define CP_WAIT1()  asm volatile("cp.async.wait_group 1;")

// ---------------------------------------------------------------------------
// fp32 -> bf16 bulk converts
// ---------------------------------------------------------------------------
__global__ void __launch_bounds__(256)
to_bf16_kernel(const float* __restrict__ src, __nv_bfloat16* __restrict__ dst, int n4)
{
    const int i = blockIdx.x * blockDim.x + threadIdx.x;
    if (i < n4) {
        const float4 v = ((const float4*)src)[i];
        uint2 w;
        w.x = pack_bf16(v.x, v.y);
        w.y = pack_bf16(v.z, v.w);
        ((uint2*)dst)[i] = w;
    }
}

// all four weights in one launch: grid.z selects which
__global__ void __launch_bounds__(256)
to_bf16_w4_kernel(const float* __restrict__ w0, const float* __restrict__ w1,
                  const float* __restrict__ w2, const float* __restrict__ w3,
                  __nv_bfloat16* __restrict__ d0, __nv_bfloat16* __restrict__ d1,
                  __nv_bfloat16* __restrict__ d2, __nv_bfloat16* __restrict__ d3,
                  int n4)
{
    const int z = blockIdx.z;
    const float* src = (z == 0) ? w0 : (z == 1) ? w1 : (z == 2) ? w2 : w3;
    __nv_bfloat16* dst = (z == 0) ? d0 : (z == 1) ? d1 : (z == 2) ? d2 : d3;
    const int i = blockIdx.x * blockDim.x + threadIdx.x;
    if (i < n4) {
        const float4 v = ((const float4*)src)[i];
        uint2 w;
        w.x = pack_bf16(v.x, v.y);
        w.y = pack_bf16(v.z, v.w);
        ((uint2*)dst)[i] = w;
    }
}

#define SSTR 20   // GEMM smem row stride in words (BK=32: 16 data words + 4 pad)
#define STG_WORDS (128 * SSTR)                 // words per stage per array
#define GEMM_SMEM_BYTES (3 * STG_WORDS * 4 * 2)  // 61440

// ---------------------------------------------------------------------------
// bf16 GEMM mainloop: C[128x128] of A[M,K] @ W[N,K]^T, K=1024, BK=32.
// 256 threads = 8 warps, warp tile 64x32. 3-stage cp.async (dynamic smem),
// ldmatrix, 1 sync per BK tile, wait_group 1 (one prefetch stays in flight).
// ---------------------------------------------------------------------------
__device__ __forceinline__ void gemm_main_bf16(const __nv_bfloat16* __restrict__ A,
                                               const __nv_bfloat16* __restrict__ Wt,
                                               uint32_t* As, uint32_t* Bs,
                                               float acc[4][4][4])
{
    const int tid  = threadIdx.x;
    const int lane = tid & 31;
    const int warp = tid >> 5;
    const int wm   = (warp >> 2) * 64;
    const int wn   = (warp & 3) * 32;
    const int m0   = blockIdx.y * 128;
    const int n0   = blockIdx.x * 128;

    // fill indexing: 2 A-chunks + 2 B-chunks per thread per stage
    const int fr0 = tid >> 2;               // rows 0..63
    const int fr1 = (256 + tid) >> 2;       // rows 64..127
    const int fc  = tid & 3;                // 16B chunk 0..3

    // ldmatrix per-thread source positions
    const int a_row  = wm + (lane & 15);
    const int a_word = (lane >> 4) * 4;
    const int b_row  = wn + (lane & 7) + ((lane & 16) >> 1);
    const int b_word = (lane & 8) ? 4 : 0;

    uint32_t aaddr[3], baddr[3], sA0[3], sA1[3], sB0[3], sB1[3];
    #pragma unroll
    for (int s = 0; s < 3; ++s) {
        uint32_t* Asb = As + s * STG_WORDS;
        uint32_t* Bsb = Bs + s * STG_WORDS;
        aaddr[s] = cvta_s(&Asb[a_row * SSTR + a_word]);
        baddr[s] = cvta_s(&Bsb[b_row * SSTR + b_word]);
        sA0[s] = cvta_s(&Asb[fr0 * SSTR + fc * 4]);
        sA1[s] = cvta_s(&Asb[fr1 * SSTR + fc * 4]);
        sB0[s] = cvta_s(&Bsb[fr0 * SSTR + fc * 4]);
        sB1[s] = cvta_s(&Bsb[fr1 * SSTR + fc * 4]);
    }

    const __nv_bfloat16* Ap0 = A  + (size_t)(m0 + fr0) * Dm + fc * 8;
    const __nv_bfloat16* Ap1 = A  + (size_t)(m0 + fr1) * Dm + fc * 8;
    const __nv_bfloat16* Bp0 = Wt + (size_t)(n0 + fr0) * Dm + fc * 8;
    const __nv_bfloat16* Bp1 = Wt + (size_t)(n0 + fr1) * Dm + fc * 8;

    // prologue: stages 0 and 1 (k-slabs 0, 1)
    CP16(sA0[0], Ap0); CP16(sA1[0], Ap1);
    CP16(sB0[0], Bp0); CP16(sB1[0], Bp1);
    CP_COMMIT();
    CP16(sA0[1], Ap0 + 32); CP16(sA1[1], Ap1 + 32);
    CP16(sB0[1], Bp0 + 32); CP16(sB1[1], Bp1 + 32);
    CP_COMMIT();

    int cur = 0;
    for (int kt = 0; kt < 32; ++kt) {
        if (kt < 31) CP_WAIT1(); else CP_WAIT0();
        __syncthreads();

        // prefetch k-slab kt+2 into the stage freed at kt-1
        if (kt + 2 <= 31) {
            int nxt = cur + 2; if (nxt >= 3) nxt -= 3;
            const int kb = (kt + 2) * 32;
            CP16(sA0[nxt], Ap0 + kb); CP16(sA1[nxt], Ap1 + kb);
            CP16(sB0[nxt], Bp0 + kb); CP16(sB1[nxt], Bp1 + kb);
            CP_COMMIT();
        }

        #pragma unroll
        for (int slab = 0; slab < 2; ++slab) {
            const uint32_t soff = slab * 8 * 4;
            uint32_t a[4][4], b[4][2];
            #pragma unroll
            for (int mi = 0; mi < 4; ++mi)
                LDSM4(a[mi][0], a[mi][1], a[mi][2], a[mi][3],
                      aaddr[cur] + (mi * 16 * SSTR) * 4 + soff);
            #pragma unroll
            for (int n2 = 0; n2 < 2; ++n2)
                LDSM4(b[2 * n2][0], b[2 * n2][1], b[2 * n2 + 1][0], b[2 * n2 + 1][1],
                      baddr[cur] + (n2 * 16 * SSTR) * 4 + soff);
            #pragma unroll
            for (int mi = 0; mi < 4; ++mi)
                #pragma unroll
                for (int ni = 0; ni < 4; ++ni)
                    mma_bf16(acc[mi][ni], a[mi], b[ni]);
        }

        if (++cur == 3) cur = 0;
    }
}

// ---------------------------------------------------------------------------
// QKV projection. grid = (8, 32, 3): z selects Q/K/V.
// ---------------------------------------------------------------------------
__global__ void __launch_bounds__(256)
gemm_qkv_kernel(const float* __restrict__ bq, const float* __restrict__ bk,
                const float* __restrict__ bv)
{
    extern __shared__ uint32_t dyn_smem[];
    uint32_t* As = dyn_smem;
    uint32_t* Bs = dyn_smem + 3 * STG_WORDS;

    const int z = blockIdx.z;
    const __nv_bfloat16* W = (z == 0) ? g_wqb : (z == 1) ? g_wkb : g_wvb;
    const float* bias      = (z == 0) ? bq : (z == 1) ? bk : bv;

    float acc[4][4][4];
    #pragma unroll
    for (int mi = 0; mi < 4; ++mi)
        #pragma unroll
        for (int ni = 0; ni < 4; ++ni) {
            acc[mi][ni][0] = 0.f; acc[mi][ni][1] = 0.f;
            acc[mi][ni][2] = 0.f; acc[mi][ni][3] = 0.f;
        }

    gemm_main_bf16(g_xb, W, As, Bs, acc);

    const int tid  = threadIdx.x;
    const int lane = tid & 31;
    const int warp = tid >> 5;
    const int wm   = (warp >> 2) * 64;
    const int wn   = (warp & 3) * 32;
    const int g    = lane >> 2;
    const int q    = lane & 3;
    const int m0   = blockIdx.y * 128;
    const int n0   = blockIdx.x * 128;

    if (z < 2) {
        __nv_bfloat16* dst = (z == 0) ? g_q : g_k;
        const float sc = (z == 0) ? 0.125f : 1.0f;
        #pragma unroll
        for (int mi = 0; mi < 4; ++mi) {
            #pragma unroll
            for (int i = 0; i < 2; ++i) {
                const int gm = m0 + wm + mi * 16 + g + i * 8;
                const int b  = gm >> 11;
                const int s  = gm & 2047;
                #pragma unroll
                for (int ni = 0; ni < 4; ++ni) {
                    const int gn0 = n0 + wn + ni * 8 + q * 2;
                    const int h   = gn0 >> 6, dd0 = gn0 & 63;
                    const uint32_t w = pack_bf16((acc[mi][ni][i * 2 + 0] + bias[gn0 + 0]) * sc,
                                                 (acc[mi][ni][i * 2 + 1] + bias[gn0 + 1]) * sc);
                    *(uint32_t*)&dst[(((size_t)(b * Hm + h) * Sm + s) * DHm) + dd0] = w;
                }
            }
        }
    } else {
        // V: [bh][d][s] scatter (2B stores)
        #pragma unroll
        for (int mi = 0; mi < 4; ++mi) {
            #pragma unroll
            for (int i = 0; i < 2; ++i) {
                const int gm = m0 + wm + mi * 16 + g + i * 8;
                const int b  = gm >> 11;
                const int s  = gm & 2047;
                #pragma unroll
                for (int ni = 0; ni < 4; ++ni) {
                    const int gn0 = n0 + wn + ni * 8 + q * 2;
                    const int h   = gn0 >> 6, dd0 = gn0 & 63;
                    const size_t base = ((size_t)(b * Hm + h) * DHm + dd0) * Sm + s;
                    g_v[base]      = __float2bfloat16_rn(acc[mi][ni][i * 2 + 0] + bias[gn0 + 0]);
                    g_v[base + Sm] = __float2bfloat16_rn(acc[mi][ni][i * 2 + 1] + bias[gn0 + 1]);
                }
            }
        }
    }
}

// ---------------------------------------------------------------------------
// Output projection + residual: y = ctx @ Wo^T + bo + x   (ctx bf16)
// ---------------------------------------------------------------------------
__global__ void __launch_bounds__(256)
gemm_oproj_kernel(const float* __restrict__ bo, const float* __restrict__ x)
{
    extern __shared__ uint32_t dyn_smem[];
    uint32_t* As = dyn_smem;
    uint32_t* Bs = dyn_smem + 3 * STG_WORDS;

    float acc[4][4][4];
    #pragma unroll
    for (int mi = 0; mi < 4; ++mi)
        #pragma unroll
        for (int ni = 0; ni < 4; ++ni) {
            acc[mi][ni][0] = 0.f; acc[mi][ni][1] = 0.f;
            acc[mi][ni][2] = 0.f; acc[mi][ni][3] = 0.f;
        }

    gemm_main_bf16(g_ctx, g_wob, As, Bs, acc);

    const int tid  = threadIdx.x;
    const int lane = tid & 31;
    const int warp = tid >> 5;
    const int wm   = (warp >> 2) * 64;
    const int wn   = (warp & 3) * 32;
    const int g    = lane >> 2;
    const int q    = lane & 3;
    const int m0   = blockIdx.y * 128;
    const int n0   = blockIdx.x * 128;

    #pragma unroll
    for (int mi = 0; mi < 4; ++mi) {
        #pragma unroll
        for (int i = 0; i < 2; ++i) {
            const int gm = m0 + wm + mi * 16 + g + i * 8;
            #pragma unroll
            for (int ni = 0; ni < 4; ++ni) {
                const int gn0 = n0 + wn + ni * 8 + q * 2;
                const size_t off = (size_t)gm * Dm + gn0;
                const float2 r = *(const float2*)&x[off];
                float2 v;
                v.x = acc[mi][ni][i * 2 + 0] + bo[gn0 + 0] + r.x;
                v.y = acc[mi][ni][i * 2 + 1] + bo[gn0 + 1] + r.y;
                *(float2*)&g_y[off] = v;
            }
        }
    }
}

// ---------------------------------------------------------------------------
// Causal flash attention (identical to measured R12 version).
// ---------------------------------------------------------------------------
#define ALD 36

__global__ void __launch_bounds__(256)
attn_kernel(const __nv_bfloat16* __restrict__ Qg, const __nv_bfloat16* __restrict__ Kg,
            const __nv_bfloat16* __restrict__ Vg, __nv_bfloat16* __restrict__ ctx)
{
    __shared__ __align__(16) uint32_t Ks[64 * ALD];
    __shared__ __align__(16) uint32_t Vt[64 * ALD];
    __shared__ __align__(16) uint32_t Ps[128 * ALD];

    const int tid  = threadIdx.x;
    const int lane = tid & 31;
    const int warp = tid >> 5;
    const int g    = lane >> 2;
    const int q    = lane & 3;
    const int bh   = blockIdx.y;
    const int qb   = (int)(gridDim.x - 1) - (int)blockIdx.x;   // heavy first
    const int qi0  = qb * 128;
    const int wrow = warp * 16;

    const __nv_bfloat16* Qbh = Qg + (size_t)bh * Sm * DHm;
    const __nv_bfloat16* Kbh = Kg + (size_t)bh * Sm * DHm;
    const __nv_bfloat16* Vbh = Vg + (size_t)bh * DHm * Sm;

    const int fr_row = (lane & 7) + ((lane & 16) >> 1);
    const int fr_wrd = (lane & 8) ? 4 : 0;
    const uint32_t ks_b = cvta_s(&Ks[fr_row * ALD + fr_wrd]);
    const uint32_t vt_b = cvta_s(&Vt[fr_row * ALD + fr_wrd]);
    const uint32_t p_a  = cvta_s(&Ps[(wrow + (lane & 15)) * ALD + (lane >> 4) * 4]);

    uint32_t qa[4][4];
    {
        const size_t r0 = (size_t)(qi0 + wrow + g) * DHm;
        const size_t r1 = r0 + 8 * DHm;
        #pragma unroll
        for (int kf = 0; kf < 4; ++kf) {
            const int d0 = kf * 16 + 2 * q;
            qa[kf][0] = *(const uint32_t*)&Qbh[r0 + d0];
            qa[kf][1] = *(const uint32_t*)&Qbh[r1 + d0];
            qa[kf][2] = *(const uint32_t*)&Qbh[r0 + d0 + 8];
            qa[kf][3] = *(const uint32_t*)&Qbh[r1 + d0 + 8];
        }
    }

    float m0 = -1e30f, m1 = -1e30f, l0 = 0.f, l1 = 0.f;
    float o[8][4];
    #pragma unroll
    for (int nf = 0; nf < 8; ++nf) {
        o[nf][0] = 0.f; o[nf][1] = 0.f; o[nf][2] = 0.f; o[nf][3] = 0.f;
    }

    const int ntiles = 2 * qb + 2;
    for (int kt = 0; kt < ntiles; ++kt) {
        const int kj0 = kt * 64;
        __syncthreads();

        #pragma unroll
        for (int it = 0; it < 2; ++it) {
            const int idx = it * 256 + tid;
            const int row = idx >> 3;
            const int cw  = idx & 7;
            *(uint4*)&Ks[row * ALD + cw * 4] =
                *(const uint4*)&Kbh[(size_t)(kj0 + row) * DHm + cw * 8];
            *(uint4*)&Vt[row * ALD + cw * 4] =
                *(const uint4*)&Vbh[(size_t)row * Sm + kj0 + cw * 8];
        }
        __syncthreads();

        float sacc[8][4];
        #pragma unroll
        for (int nf = 0; nf < 8; ++nf) {
            sacc[nf][0] = 0.f; sacc[nf][1] = 0.f; sacc[nf][2] = 0.f; sacc[nf][3] = 0.f;
        }
        #pragma unroll
        for (int kf = 0; kf < 4; ++kf) {
            #pragma unroll
            for (int n2 = 0; n2 < 4; ++n2) {
                uint32_t b4[4];
                LDSM4(b4[0], b4[1], b4[2], b4[3],
                      ks_b + (n2 * 16 * ALD + kf * 8) * 4);
                mma_bf16(sacc[2 * n2],     qa[kf], b4);
                mma_bf16(sacc[2 * n2 + 1], qa[kf], b4 + 2);
            }
        }

        if (kt >= 2 * qb) {
            const int rg0 = qi0 + wrow + g, rg1 = rg0 + 8;
            #pragma unroll
            for (int nf = 0; nf < 8; ++nf) {
                const int cg = kj0 + nf * 8 + 2 * q;
                if (cg     > rg0) sacc[nf][0] = -1e30f;
                if (cg + 1 > rg0) sacc[nf][1] = -1e30f;
                if (cg     > rg1) sacc[nf][2] = -1e30f;
                if (cg + 1 > rg1) sacc[nf][3] = -1e30f;
            }
        }

        float mx0 = -1e30f, mx1 = -1e30f;
        #pragma unroll
        for (int nf = 0; nf < 8; ++nf) {
            mx0 = fmaxf(mx0, fmaxf(sacc[nf][0], sacc[nf][1]));
            mx1 = fmaxf(mx1, fmaxf(sacc[nf][2], sacc[nf][3]));
        }
        mx0 = fmaxf(mx0, __shfl_xor_sync(0xffffffffu, mx0, 1));
        mx0 = fmaxf(mx0, __shfl_xor_sync(0xffffffffu, mx0, 2));
        mx1 = fmaxf(mx1, __shfl_xor_sync(0xffffffffu, mx1, 1));
        mx1 = fmaxf(mx1, __shfl_xor_sync(0xffffffffu, mx1, 2));

        const float mn0 = fmaxf(m0, mx0);
        const float mn1 = fmaxf(m1, mx1);
        const float al0 = __expf(m0 - mn0);
        const float al1 = __expf(m1 - mn1);
        m0 = mn0; m1 = mn1;

        float rs0 = 0.f, rs1 = 0.f;
        #pragma unroll
        for (int nf = 0; nf < 8; ++nf) {
            sacc[nf][0] = __expf(sacc[nf][0] - mn0);
            sacc[nf][1] = __expf(sacc[nf][1] - mn0);
            sacc[nf][2] = __expf(sacc[nf][2] - mn1);
            sacc[nf][3] = __expf(sacc[nf][3] - mn1);
            rs0 += sacc[nf][0] + sacc[nf][1];
            rs1 += sacc[nf][2] + sacc[nf][3];
        }
        rs0 += __shfl_xor_sync(0xffffffffu, rs0, 1);
        rs0 += __shfl_xor_sync(0xffffffffu, rs0, 2);
        rs1 += __shfl_xor_sync(0xffffffffu, rs1, 1);
        rs1 += __shfl_xor_sync(0xffffffffu, rs1, 2);

        l0 = l0 * al0 + rs0;
        l1 = l1 * al1 + rs1;
        #pragma unroll
        for (int nf = 0; nf < 8; ++nf) {
            o[nf][0] *= al0; o[nf][1] *= al0;
            o[nf][2] *= al1; o[nf][3] *= al1;
        }

        {
            const int r0l = wrow + g, r1l = r0l + 8;
            #pragma unroll
            for (int nf = 0; nf < 8; ++nf) {
                Ps[r0l * ALD + nf * 4 + q] = pack_bf16(sacc[nf][0], sacc[nf][1]);
                Ps[r1l * ALD + nf * 4 + q] = pack_bf16(sacc[nf][2], sacc[nf][3]);
            }
        }
        __syncwarp();

        #pragma unroll
        for (int kf = 0; kf < 4; ++kf) {
            uint32_t a4[4];
            LDSM4(a4[0], a4[1], a4[2], a4[3], p_a + (kf * 8) * 4);
            #pragma unroll
            for (int n2 = 0; n2 < 4; ++n2) {
                uint32_t b4[4];
                LDSM4(b4[0], b4[1], b4[2], b4[3],
                      vt_b + (n2 * 16 * ALD + kf * 8) * 4);
                mma_bf16(o[2 * n2],     a4, b4);
                mma_bf16(o[2 * n2 + 1], a4, b4 + 2);
            }
        }
    }

    const int b = bh >> 4, h = bh & 15;
    const float inv0 = 1.0f / l0;
    const float inv1 = 1.0f / l1;
    const int s0 = qi0 + wrow + g;
    #pragma unroll
    for (int nf = 0; nf < 8; ++nf) {
        const int dd = h * DHm + nf * 8 + 2 * q;
        *(uint32_t*)&ctx[((size_t)(b * Sm + s0)) * Dm + dd] =
            pack_bf16(o[nf][0] * inv0, o[nf][1] * inv0);
        *(uint32_t*)&ctx[((size_t)(b * Sm + s0 + 8)) * Dm + dd] =
            pack_bf16(o[nf][2] * inv1, o[nf][3] * inv1);
    }
}

// ---------------------------------------------------------------------------
// LayerNorm over last dim (1024). One block per row, 256 threads x 4 floats.
// ---------------------------------------------------------------------------
__global__ void __launch_bounds__(256)
ln_kernel(const float* __restrict__ y, const float* __restrict__ gam,
          const float* __restrict__ bet, float* __restrict__ out)
{
    __shared__ float red[2][8];
    const int row = blockIdx.x;
    const int tid = threadIdx.x;

    const float4 v = *(const float4*)&y[(size_t)row * Dm + tid * 4];
    float s  = v.x + v.y + v.z + v.w;
    float ss = v.x * v.x + v.y * v.y + v.z * v.z + v.w * v.w;

    #pragma unroll
    for (int off = 16; off > 0; off >>= 1) {
        s  += __shfl_xor_sync(0xffffffffu, s, off);
        ss += __shfl_xor_sync(0xffffffffu, ss, off);
    }
    const int wid = tid >> 5, lane = tid & 31;
    if (lane == 0) { red[0][wid] = s; red[1][wid] = ss; }
    __syncthreads();
    if (tid == 0) {
        float S = 0.f, SS = 0.f;
        #pragma unroll
        for (int w = 0; w < 8; ++w) { S += red[0][w]; SS += red[1][w]; }
        red[0][0] = S; red[1][0] = SS;
    }
    __syncthreads();

    const float mu   = red[0][0] * (1.0f / Dm);
    const float var  = red[1][0] * (1.0f / Dm) - mu * mu;
    const float rstd = rsqrtf(var + 1e-5f);

    const float4 g4 = *(const float4*)&gam[tid * 4];
    const float4 b4 = *(const float4*)&bet[tid * 4];
    float4 r;
    r.x = (v.x - mu) * rstd * g4.x + b4.x;
    r.y = (v.y - mu) * rstd * g4.y + b4.y;
    r.z = (v.z - mu) * rstd * g4.z + b4.z;
    r.w = (v.w - mu) * rstd * g4.w + b4.w;
    *(float4*)&out[(size_t)row * Dm + tid * 4] = r;
}

// ---------------------------------------------------------------------------
extern "C" void kernel_launch(void* const* d_in, const int* in_sizes, int n_in,
                              void* d_out, int out_size)
{
    const float* x    = (const float*)d_in[0];
    const float* Wq   = (const float*)d_in[1];
    const float* bq   = (const float*)d_in[2];
    const float* Wk   = (const float*)d_in[3];
    const float* bk   = (const float*)d_in[4];
    const float* Wv   = (const float*)d_in[5];
    const float* bv   = (const float*)d_in[6];
    const float* Wo   = (const float*)d_in[7];
    const float* bo   = (const float*)d_in[8];
    const float* ln_g = (const float*)d_in[9];
    const float* ln_b = (const float*)d_in[10];
    float* out = (float*)d_out;

    __nv_bfloat16 *xb_p, *wq_p, *wk_p, *wv_p, *wo_p, *q_p, *k_p, *v_p, *ctx_p;
    float* y_p;
    cudaGetSymbolAddress((void**)&xb_p,  g_xb);
    cudaGetSymbolAddress((void**)&wq_p,  g_wqb);
    cudaGetSymbolAddress((void**)&wk_p,  g_wkb);
    cudaGetSymbolAddress((void**)&wv_p,  g_wvb);
    cudaGetSymbolAddress((void**)&wo_p,  g_wob);
    cudaGetSymbolAddress((void**)&q_p,   g_q);
    cudaGetSymbolAddress((void**)&k_p,   g_k);
    cudaGetSymbolAddress((void**)&v_p,   g_v);
    cudaGetSymbolAddress((void**)&ctx_p, g_ctx);
    cudaGetSymbolAddress((void**)&y_p,   g_y);

    // >48KB dynamic smem: set attribute unconditionally (idempotent, host-side)
    cudaFuncSetAttribute(gemm_qkv_kernel,
                         cudaFuncAttributeMaxDynamicSharedMemorySize, GEMM_SMEM_BYTES);
    cudaFuncSetAttribute(gemm_oproj_kernel,
                         cudaFuncAttributeMaxDynamicSharedMemorySize, GEMM_SMEM_BYTES);

    const int nx4 = Bm * Sm * Dm / 4;
    const int nw4 = Dm * Dm / 4;
    to_bf16_kernel<<<(nx4 + 255) / 256, 256>>>(x, xb_p, nx4);
    to_bf16_w4_kernel<<<dim3((nw4 + 255) / 256, 1, 4), 256>>>(
        Wq, Wk, Wv, Wo, wq_p, wk_p, wv_p, wo_p, nw4);

    gemm_qkv_kernel<<<dim3(8, 32, 3), 256, GEMM_SMEM_BYTES>>>(bq, bk, bv);
    attn_kernel<<<dim3(16, 32), 256>>>(q_p, k_p, v_p, ctx_p);
    gemm_oproj_kernel<<<dim3(8, 32), 256, GEMM_SMEM_BYTES>>>(bo, x);
    ln_kernel<<<4096, 256>>>(y_p, ln_g, ln_b, out);
}